// round 1
// baseline (speedup 1.0000x reference)
#include <cuda_runtime.h>
#include <math.h>

// Problem constants
#define BNUM 16
#define HW   1024          // 32*32 spatial positions
#define C    512
#define G    32
#define CG   16            // channels per group
#define NQKV 1536          // C * 3
#define MTOT (BNUM * HW)   // 16384

// Scratch (static device allocations are allowed; cudaMalloc is not)
__device__ float g_x[MTOT * C];        // 32 MB group-normed activations
__device__ float g_q[MTOT * C];        // 32 MB
__device__ float g_k[MTOT * C];        // 32 MB
__device__ float g_v[MTOT * C];        // 32 MB
__device__ float g_s[BNUM * HW * HW];  // 64 MB attention scores/probs
__device__ float g_o[MTOT * C];        // 32 MB attention output

// ---------------------------------------------------------------------------
// GroupNorm: one block per (batch, group). Reduce 1024*16 = 16384 elements.
// ---------------------------------------------------------------------------
__global__ void groupnorm_kernel(const float* __restrict__ in,
                                 const float* __restrict__ gamma,
                                 const float* __restrict__ beta) {
    int b = blockIdx.x >> 5;
    int g = blockIdx.x & 31;
    int tid = threadIdx.x;
    const float* base = in + (size_t)b * HW * C + g * CG;
    float s = 0.f, ss = 0.f;
    for (int e = tid; e < HW * CG; e += 256) {
        int pos = e >> 4;
        int c = e & 15;
        float v = base[(size_t)pos * C + c];
        s += v;
        ss += v * v;
    }
    __shared__ float rs[256], rss[256];
    rs[tid] = s; rss[tid] = ss;
    __syncthreads();
    for (int o = 128; o > 0; o >>= 1) {
        if (tid < o) { rs[tid] += rs[tid + o]; rss[tid] += rss[tid + o]; }
        __syncthreads();
    }
    const float invN = 1.0f / (HW * CG);
    float mean = rs[0] * invN;
    float var  = rss[0] * invN - mean * mean;
    float rstd = rsqrtf(var + 1e-3f);
    float* outb = g_x + (size_t)b * HW * C + g * CG;
    for (int e = tid; e < HW * CG; e += 256) {
        int pos = e >> 4;
        int c = e & 15;
        float v = base[(size_t)pos * C + c];
        outb[(size_t)pos * C + c] =
            (v - mean) * rstd * gamma[g * CG + c] + beta[g * CG + c];
    }
}

// ---------------------------------------------------------------------------
// QKV GEMM: g_x [16384 x 512] @ W_qkv [512 x 1536] (+bias), scatter to q/k/v.
// 64x64 block tile, BK=16, 256 threads, 4x4 per-thread microtile.
// ---------------------------------------------------------------------------
__global__ void qkv_gemm(const float* __restrict__ Wq,
                         const float* __restrict__ bq) {
    __shared__ float As[16][64];
    __shared__ float Bs[16][64];
    int tid = threadIdx.x;
    int tx = tid & 15, ty = tid >> 4;
    int mStart = blockIdx.y * 64;
    int nStart = blockIdx.x * 64;
    float acc[4][4] = {};
    int aRow = tid >> 2, aCol = (tid & 3) << 2;   // A tile: 64 rows x 16 cols
    int bRow = tid >> 4, bCol = (tid & 15) << 2;  // B tile: 16 rows x 64 cols

    for (int k0 = 0; k0 < C; k0 += 16) {
        float4 av = *(const float4*)(g_x + (size_t)(mStart + aRow) * C + k0 + aCol);
        As[aCol + 0][aRow] = av.x; As[aCol + 1][aRow] = av.y;
        As[aCol + 2][aRow] = av.z; As[aCol + 3][aRow] = av.w;
        float4 bv = *(const float4*)(Wq + (size_t)(k0 + bRow) * NQKV + nStart + bCol);
        *(float4*)&Bs[bRow][bCol] = bv;
        __syncthreads();
#pragma unroll
        for (int kk = 0; kk < 16; kk++) {
            float4 a  = *(float4*)&As[kk][ty * 4];
            float4 bb = *(float4*)&Bs[kk][tx * 4];
            float ar[4] = {a.x, a.y, a.z, a.w};
            float br[4] = {bb.x, bb.y, bb.z, bb.w};
#pragma unroll
            for (int i = 0; i < 4; i++)
#pragma unroll
                for (int j = 0; j < 4; j++) acc[i][j] += ar[i] * br[j];
        }
        __syncthreads();
    }
#pragma unroll
    for (int i = 0; i < 4; i++) {
        int m = mStart + ty * 4 + i;
#pragma unroll
        for (int j = 0; j < 4; j++) {
            int n = nStart + tx * 4 + j;
            float v = acc[i][j] + bq[n];
            int e = n % 3, a = n / 3;
            float* dst = (e == 0) ? g_q : (e == 1) ? g_k : g_v;
            dst[(size_t)m * C + a] = v;
        }
    }
}

// ---------------------------------------------------------------------------
// S = Q @ K^T, per batch (NT GEMM). M = N = 1024, K = 512.
// ---------------------------------------------------------------------------
__global__ void qk_gemm() {
    int b = blockIdx.z;
    const float* Q = g_q + (size_t)b * HW * C;
    const float* K = g_k + (size_t)b * HW * C;
    float* S = g_s + (size_t)b * HW * HW;
    __shared__ float As[16][64];
    __shared__ float Bs[16][64];
    int tid = threadIdx.x;
    int tx = tid & 15, ty = tid >> 4;
    int mStart = blockIdx.y * 64;
    int nStart = blockIdx.x * 64;
    float acc[4][4] = {};
    int aRow = tid >> 2, aCol = (tid & 3) << 2;  // 64 rows x 16 cols (both tiles)

    for (int k0 = 0; k0 < C; k0 += 16) {
        float4 av = *(const float4*)(Q + (size_t)(mStart + aRow) * C + k0 + aCol);
        As[aCol + 0][aRow] = av.x; As[aCol + 1][aRow] = av.y;
        As[aCol + 2][aRow] = av.z; As[aCol + 3][aRow] = av.w;
        float4 bv = *(const float4*)(K + (size_t)(nStart + aRow) * C + k0 + aCol);
        Bs[aCol + 0][aRow] = bv.x; Bs[aCol + 1][aRow] = bv.y;
        Bs[aCol + 2][aRow] = bv.z; Bs[aCol + 3][aRow] = bv.w;
        __syncthreads();
#pragma unroll
        for (int kk = 0; kk < 16; kk++) {
            float4 a  = *(float4*)&As[kk][ty * 4];
            float4 bb = *(float4*)&Bs[kk][tx * 4];
            float ar[4] = {a.x, a.y, a.z, a.w};
            float br[4] = {bb.x, bb.y, bb.z, bb.w};
#pragma unroll
            for (int i = 0; i < 4; i++)
#pragma unroll
                for (int j = 0; j < 4; j++) acc[i][j] += ar[i] * br[j];
        }
        __syncthreads();
    }
#pragma unroll
    for (int i = 0; i < 4; i++) {
        int m = mStart + ty * 4 + i;
#pragma unroll
        for (int j = 0; j < 4; j++) {
            int n = nStart + tx * 4 + j;
            S[(size_t)m * HW + n] = acc[i][j];
        }
    }
}

// ---------------------------------------------------------------------------
// Row softmax over 1024 cols (scale applied here). One block per row.
// ---------------------------------------------------------------------------
__global__ void softmax_kernel() {
    const float scale = 0.04419417382415922f;  // 512^-0.5
    size_t row = blockIdx.x;
    float* p = g_s + row * HW;
    int tid = threadIdx.x;
    float4 v = ((float4*)p)[tid];
    v.x *= scale; v.y *= scale; v.z *= scale; v.w *= scale;

    __shared__ float red[256];
    float m = fmaxf(fmaxf(v.x, v.y), fmaxf(v.z, v.w));
    red[tid] = m;
    __syncthreads();
    for (int o = 128; o > 0; o >>= 1) {
        if (tid < o) red[tid] = fmaxf(red[tid], red[tid + o]);
        __syncthreads();
    }
    m = red[0];
    __syncthreads();

    float e0 = __expf(v.x - m), e1 = __expf(v.y - m);
    float e2 = __expf(v.z - m), e3 = __expf(v.w - m);
    red[tid] = e0 + e1 + e2 + e3;
    __syncthreads();
    for (int o = 128; o > 0; o >>= 1) {
        if (tid < o) red[tid] += red[tid + o];
        __syncthreads();
    }
    float inv = 1.0f / red[0];
    float4 w = make_float4(e0 * inv, e1 * inv, e2 * inv, e3 * inv);
    ((float4*)p)[tid] = w;
}

// ---------------------------------------------------------------------------
// O = P @ V, per batch (NN GEMM). M = 1024, N = 512, K = 1024.
// ---------------------------------------------------------------------------
__global__ void pv_gemm() {
    int b = blockIdx.z;
    const float* P = g_s + (size_t)b * HW * HW;
    const float* V = g_v + (size_t)b * HW * C;
    float* O = g_o + (size_t)b * HW * C;
    __shared__ float As[16][64];
    __shared__ float Bs[16][64];
    int tid = threadIdx.x;
    int tx = tid & 15, ty = tid >> 4;
    int mStart = blockIdx.y * 64;
    int nStart = blockIdx.x * 64;
    float acc[4][4] = {};
    int aRow = tid >> 2, aCol = (tid & 3) << 2;
    int bRow = tid >> 4, bCol = (tid & 15) << 2;

    for (int k0 = 0; k0 < HW; k0 += 16) {
        float4 av = *(const float4*)(P + (size_t)(mStart + aRow) * HW + k0 + aCol);
        As[aCol + 0][aRow] = av.x; As[aCol + 1][aRow] = av.y;
        As[aCol + 2][aRow] = av.z; As[aCol + 3][aRow] = av.w;
        float4 bv = *(const float4*)(V + (size_t)(k0 + bRow) * C + nStart + bCol);
        *(float4*)&Bs[bRow][bCol] = bv;
        __syncthreads();
#pragma unroll
        for (int kk = 0; kk < 16; kk++) {
            float4 a  = *(float4*)&As[kk][ty * 4];
            float4 bb = *(float4*)&Bs[kk][tx * 4];
            float ar[4] = {a.x, a.y, a.z, a.w};
            float br[4] = {bb.x, bb.y, bb.z, bb.w};
#pragma unroll
            for (int i = 0; i < 4; i++)
#pragma unroll
                for (int j = 0; j < 4; j++) acc[i][j] += ar[i] * br[j];
        }
        __syncthreads();
    }
#pragma unroll
    for (int i = 0; i < 4; i++) {
        int m = mStart + ty * 4 + i;
#pragma unroll
        for (int j = 0; j < 4; j++) {
            int n = nStart + tx * 4 + j;
            O[(size_t)m * C + n] = acc[i][j];
        }
    }
}

// ---------------------------------------------------------------------------
// Final: g_o [16384 x 512] @ W_out [512 x 512] + b_out + residual -> d_out.
// ---------------------------------------------------------------------------
__global__ void out_gemm(const float* __restrict__ Wo,
                         const float* __restrict__ bo,
                         const float* __restrict__ resid,
                         float* __restrict__ out) {
    __shared__ float As[16][64];
    __shared__ float Bs[16][64];
    int tid = threadIdx.x;
    int tx = tid & 15, ty = tid >> 4;
    int mStart = blockIdx.y * 64;
    int nStart = blockIdx.x * 64;
    float acc[4][4] = {};
    int aRow = tid >> 2, aCol = (tid & 3) << 2;
    int bRow = tid >> 4, bCol = (tid & 15) << 2;

    for (int k0 = 0; k0 < C; k0 += 16) {
        float4 av = *(const float4*)(g_o + (size_t)(mStart + aRow) * C + k0 + aCol);
        As[aCol + 0][aRow] = av.x; As[aCol + 1][aRow] = av.y;
        As[aCol + 2][aRow] = av.z; As[aCol + 3][aRow] = av.w;
        float4 bv = *(const float4*)(Wo + (size_t)(k0 + bRow) * C + nStart + bCol);
        *(float4*)&Bs[bRow][bCol] = bv;
        __syncthreads();
#pragma unroll
        for (int kk = 0; kk < 16; kk++) {
            float4 a  = *(float4*)&As[kk][ty * 4];
            float4 bb = *(float4*)&Bs[kk][tx * 4];
            float ar[4] = {a.x, a.y, a.z, a.w};
            float br[4] = {bb.x, bb.y, bb.z, bb.w};
#pragma unroll
            for (int i = 0; i < 4; i++)
#pragma unroll
                for (int j = 0; j < 4; j++) acc[i][j] += ar[i] * br[j];
        }
        __syncthreads();
    }
#pragma unroll
    for (int i = 0; i < 4; i++) {
        int m = mStart + ty * 4 + i;
#pragma unroll
        for (int j = 0; j < 4; j++) {
            int n = nStart + tx * 4 + j;
            out[(size_t)m * C + n] = acc[i][j] + bo[n] + resid[(size_t)m * C + n];
        }
    }
}

// ---------------------------------------------------------------------------
extern "C" void kernel_launch(void* const* d_in, const int* in_sizes, int n_in,
                              void* d_out, int out_size) {
    (void)in_sizes; (void)n_in; (void)out_size;
    const float* inputs = (const float*)d_in[0];
    const float* gamma  = (const float*)d_in[1];
    const float* beta   = (const float*)d_in[2];
    const float* Wqkv   = (const float*)d_in[3];
    const float* bqkv   = (const float*)d_in[4];
    const float* Wout   = (const float*)d_in[5];
    const float* bout   = (const float*)d_in[6];
    float* out = (float*)d_out;

    groupnorm_kernel<<<BNUM * G, 256>>>(inputs, gamma, beta);
    qkv_gemm<<<dim3(NQKV / 64, MTOT / 64), 256>>>(Wqkv, bqkv);
    qk_gemm<<<dim3(HW / 64, HW / 64, BNUM), 256>>>();
    softmax_kernel<<<BNUM * HW, 256>>>();
    pv_gemm<<<dim3(C / 64, HW / 64, BNUM), 256>>>();
    out_gemm<<<dim3(C / 64, MTOT / 64), 256>>>(Wout, bout, inputs, out);
}

// round 3
// speedup vs baseline: 3.7079x; 3.7079x over previous
#include <cuda_runtime.h>
#include <cuda_fp16.h>
#include <cstdint>
#include <cstddef>
#include <math.h>

#define BNUM 16
#define HW   1024
#define C    512
#define G    32
#define CG   16
#define NQKV 1536
#define MTOT (BNUM * HW)
#define SCALE 0.044194173824159216f   // 512^-0.5

// fp16 scratch (static device arrays: allowed)
__device__ __half g_xh[MTOT * C];
__device__ __half g_qh[MTOT * C];
__device__ __half g_kh[MTOT * C];
__device__ __half g_vh[MTOT * C];
__device__ __half g_sh[(size_t)BNUM * HW * HW];
__device__ __half g_oh[MTOT * C];
__device__ __half g_wqkvh[C * NQKV];
__device__ __half g_wouth[C * C];

// ---------------------------------------------------------------------------
// helpers
// ---------------------------------------------------------------------------
__device__ __forceinline__ uint32_t smaddr(const void* p) {
    return (uint32_t)__cvta_generic_to_shared(p);
}
__device__ __forceinline__ void ldsm4(uint32_t a, uint32_t& r0, uint32_t& r1,
                                      uint32_t& r2, uint32_t& r3) {
    asm volatile("ldmatrix.sync.aligned.m8n8.x4.shared.b16 {%0,%1,%2,%3},[%4];"
                 : "=r"(r0), "=r"(r1), "=r"(r2), "=r"(r3) : "r"(a));
}
__device__ __forceinline__ void ldsm4t(uint32_t a, uint32_t& r0, uint32_t& r1,
                                       uint32_t& r2, uint32_t& r3) {
    asm volatile("ldmatrix.sync.aligned.m8n8.x4.trans.shared.b16 {%0,%1,%2,%3},[%4];"
                 : "=r"(r0), "=r"(r1), "=r"(r2), "=r"(r3) : "r"(a));
}
__device__ __forceinline__ void mma16816(float* d, const uint32_t* a, const uint32_t* b) {
    asm volatile(
        "mma.sync.aligned.m16n8k16.row.col.f32.f16.f16.f32 "
        "{%0,%1,%2,%3},{%4,%5,%6,%7},{%8,%9},{%0,%1,%2,%3};"
        : "+f"(d[0]), "+f"(d[1]), "+f"(d[2]), "+f"(d[3])
        : "r"(a[0]), "r"(a[1]), "r"(a[2]), "r"(a[3]), "r"(b[0]), "r"(b[1]));
}
#define CPA16(dst, src) \
    asm volatile("cp.async.cg.shared.global [%0],[%1],16;" ::"r"(dst), "l"(src))
#define CPCOMMIT() asm volatile("cp.async.commit_group;")
#define CPWAIT0()  asm volatile("cp.async.wait_group 0;")

// ---------------------------------------------------------------------------
// weight fp32 -> fp16 converters
// ---------------------------------------------------------------------------
__global__ void f2h_wqkv(const float* __restrict__ s) {
    int i = blockIdx.x * 256 + threadIdx.x;
    if (i < C * NQKV) g_wqkvh[i] = __float2half_rn(s[i]);
}
__global__ void f2h_wout(const float* __restrict__ s) {
    int i = blockIdx.x * 256 + threadIdx.x;
    if (i < C * C) g_wouth[i] = __float2half_rn(s[i]);
}

// ---------------------------------------------------------------------------
// GroupNorm -> fp16 g_xh
// ---------------------------------------------------------------------------
__global__ void groupnorm_kernel(const float* __restrict__ in,
                                 const float* __restrict__ gamma,
                                 const float* __restrict__ beta) {
    int b = blockIdx.x >> 5;
    int g = blockIdx.x & 31;
    int tid = threadIdx.x;
    const float* base = in + (size_t)b * HW * C + g * CG;
    float s = 0.f, ss = 0.f;
    for (int e = tid; e < HW * CG; e += 256) {
        int pos = e >> 4, c = e & 15;
        float v = base[(size_t)pos * C + c];
        s += v; ss += v * v;
    }
    __shared__ float rs[256], rss[256];
    rs[tid] = s; rss[tid] = ss;
    __syncthreads();
    for (int o = 128; o > 0; o >>= 1) {
        if (tid < o) { rs[tid] += rs[tid + o]; rss[tid] += rss[tid + o]; }
        __syncthreads();
    }
    const float invN = 1.0f / (HW * CG);
    float mean = rs[0] * invN;
    float var  = rss[0] * invN - mean * mean;
    float rstd = rsqrtf(var + 1e-3f);
    __half* outb = g_xh + (size_t)b * HW * C + g * CG;
    for (int e = tid; e < HW * CG; e += 256) {
        int pos = e >> 4, c = e & 15;
        float v = base[(size_t)pos * C + c];
        outb[(size_t)pos * C + c] =
            __float2half_rn((v - mean) * rstd * gamma[g * CG + c] + beta[g * CG + c]);
    }
}

// ---------------------------------------------------------------------------
// Unified fp16 tensor-core GEMM.
// EPI 0: g_xh[16384x512] @ g_wqkvh[512x1536]  -> scatter q/k/v (q scaled)
// EPI 1: Q @ K^T per batch (NT), store fp16 scores
// EPI 2: P @ V per batch (NN), store fp16 O
// EPI 3: O @ W_out + bias + residual -> fp32 out
// ---------------------------------------------------------------------------
template <int EPI>
__global__ void __launch_bounds__(256, 1)
gemm_mma(const float* __restrict__ bias,
         const float* __restrict__ resid,
         float* __restrict__ outF) {
    constexpr bool NT  = (EPI == 1);
    constexpr int  K   = (EPI == 2) ? 1024 : 512;
    constexpr int  LDA = (EPI == 2) ? 1024 : 512;
    constexpr int  LDB = (EPI == 0) ? 1536 : 512;

    __shared__ __half As[2][128][40];
    __shared__ __half Bs[2][NT ? 128 : 32][NT ? 40 : 136];

    int tid = threadIdx.x, lane = tid & 31, warp = tid >> 5;
    int wm = warp & 3, wn = warp >> 2;
    int z = blockIdx.z;
    int m0 = blockIdx.y * 128, n0 = blockIdx.x * 128;

    const __half* A;
    const __half* B;
    if constexpr (EPI == 0)      { A = g_xh;                          B = g_wqkvh; }
    else if constexpr (EPI == 1) { A = g_qh + (size_t)z * HW * C;     B = g_kh + (size_t)z * HW * C; }
    else if constexpr (EPI == 2) { A = g_sh + (size_t)z * HW * HW;    B = g_vh + (size_t)z * HW * C; }
    else                         { A = g_oh;                          B = g_wouth; }

    float acc[2][8][4] = {};

    auto load = [&](int kt, int st) {
        int k0 = kt * 32;
#pragma unroll
        for (int i = 0; i < 2; i++) {
            int c = tid + i * 256;
            int r = c >> 2, col = (c & 3) * 8;
            CPA16(smaddr(&As[st][r][col]), A + (size_t)(m0 + r) * LDA + k0 + col);
        }
        if constexpr (NT) {
#pragma unroll
            for (int i = 0; i < 2; i++) {
                int c = tid + i * 256;
                int r = c >> 2, col = (c & 3) * 8;
                CPA16(smaddr(&Bs[st][r][col]), B + (size_t)(n0 + r) * LDB + k0 + col);
            }
        } else {
#pragma unroll
            for (int i = 0; i < 2; i++) {
                int c = tid + i * 256;
                int r = c >> 4, col = (c & 15) * 8;
                CPA16(smaddr(&Bs[st][r][col]), B + (size_t)(k0 + r) * LDB + n0 + col);
            }
        }
    };

    load(0, 0);
    CPCOMMIT();
    constexpr int KT = K / 32;
    for (int kt = 0; kt < KT; kt++) {
        CPWAIT0();
        __syncthreads();
        if (kt + 1 < KT) { load(kt + 1, (kt + 1) & 1); CPCOMMIT(); }
        int st = kt & 1;
#pragma unroll
        for (int ks = 0; ks < 32; ks += 16) {
            uint32_t a[2][4], b[8][2];
#pragma unroll
            for (int mt = 0; mt < 2; mt++) {
                int r = wm * 32 + mt * 16 + (lane & 15);
                int col = ks + ((lane >> 4) << 3);
                ldsm4(smaddr(&As[st][r][col]), a[mt][0], a[mt][1], a[mt][2], a[mt][3]);
            }
            if constexpr (NT) {
#pragma unroll
                for (int ng = 0; ng < 4; ng++) {
                    int r = wn * 64 + ng * 16 + (lane & 15);
                    int col = ks + ((lane >> 4) << 3);
                    uint32_t r0, r1, r2, r3;
                    ldsm4(smaddr(&Bs[st][r][col]), r0, r1, r2, r3);
                    b[2 * ng][0] = r0; b[2 * ng][1] = r2;
                    b[2 * ng + 1][0] = r1; b[2 * ng + 1][1] = r3;
                }
            } else {
#pragma unroll
                for (int ng = 0; ng < 4; ng++) {
                    int r = ks + (lane & 15);
                    int col = wn * 64 + ng * 16 + ((lane >> 4) << 3);
                    uint32_t r0, r1, r2, r3;
                    ldsm4t(smaddr(&Bs[st][r][col]), r0, r1, r2, r3);
                    b[2 * ng][0] = r0; b[2 * ng][1] = r1;
                    b[2 * ng + 1][0] = r2; b[2 * ng + 1][1] = r3;
                }
            }
#pragma unroll
            for (int mt = 0; mt < 2; mt++)
#pragma unroll
                for (int nt = 0; nt < 8; nt++) mma16816(acc[mt][nt], a[mt], b[nt]);
        }
    }

    // epilogue
#pragma unroll
    for (int mt = 0; mt < 2; mt++) {
#pragma unroll
        for (int nt = 0; nt < 8; nt++) {
            int r  = m0 + wm * 32 + mt * 16 + (lane >> 2);
            int cc = n0 + wn * 64 + nt * 8 + (lane & 3) * 2;
            float* v = acc[mt][nt];
            if constexpr (EPI == 0) {
#pragma unroll
                for (int h = 0; h < 2; h++) {
                    int rr = r + h * 8;
#pragma unroll
                    for (int j = 0; j < 2; j++) {
                        int n = cc + j;
                        float val = v[h * 2 + j] + bias[n];
                        int e = n % 3, ch = n / 3;
                        __half hv = __float2half_rn(e == 0 ? val * SCALE : val);
                        __half* dst = (e == 0) ? g_qh : ((e == 1) ? g_kh : g_vh);
                        dst[(size_t)rr * C + ch] = hv;
                    }
                }
            } else if constexpr (EPI == 1) {
                size_t base = (size_t)z * HW * HW;
                *(__half2*)&g_sh[base + (size_t)r * HW + cc] =
                    __floats2half2_rn(v[0], v[1]);
                *(__half2*)&g_sh[base + (size_t)(r + 8) * HW + cc] =
                    __floats2half2_rn(v[2], v[3]);
            } else if constexpr (EPI == 2) {
                size_t base = (size_t)z * HW * C;
                *(__half2*)&g_oh[base + (size_t)r * C + cc] =
                    __floats2half2_rn(v[0], v[1]);
                *(__half2*)&g_oh[base + (size_t)(r + 8) * C + cc] =
                    __floats2half2_rn(v[2], v[3]);
            } else {
                outF[(size_t)r * C + cc]     = v[0] + bias[cc]     + resid[(size_t)r * C + cc];
                outF[(size_t)r * C + cc + 1] = v[1] + bias[cc + 1] + resid[(size_t)r * C + cc + 1];
                outF[(size_t)(r + 8) * C + cc]     = v[2] + bias[cc]     + resid[(size_t)(r + 8) * C + cc];
                outF[(size_t)(r + 8) * C + cc + 1] = v[3] + bias[cc + 1] + resid[(size_t)(r + 8) * C + cc + 1];
            }
        }
    }
}

// ---------------------------------------------------------------------------
// fp16 in-place row softmax over 1024 cols (scale already folded into Q)
// ---------------------------------------------------------------------------
__global__ void softmax_h() {
    size_t row = blockIdx.x;
    uint2* p = (uint2*)(g_sh + row * HW);
    int tid = threadIdx.x, lane = tid & 31, warp = tid >> 5;
    uint2 raw = p[tid];
    __half2 h0 = *(__half2*)&raw.x, h1 = *(__half2*)&raw.y;
    float2 f0 = __half22float2(h0), f1 = __half22float2(h1);

    float m = fmaxf(fmaxf(f0.x, f0.y), fmaxf(f1.x, f1.y));
#pragma unroll
    for (int o = 16; o; o >>= 1) m = fmaxf(m, __shfl_xor_sync(0xffffffffu, m, o));
    __shared__ float sred[8];
    if (lane == 0) sred[warp] = m;
    __syncthreads();
    if (warp == 0) {
        float t = (lane < 8) ? sred[lane] : -1e30f;
#pragma unroll
        for (int o = 4; o; o >>= 1) t = fmaxf(t, __shfl_xor_sync(0xffffffffu, t, o));
        if (lane == 0) sred[0] = t;
    }
    __syncthreads();
    float m_final = sred[0];
    __syncthreads();

    float e0 = __expf(f0.x - m_final), e1 = __expf(f0.y - m_final);
    float e2 = __expf(f1.x - m_final), e3 = __expf(f1.y - m_final);
    float s = e0 + e1 + e2 + e3;
#pragma unroll
    for (int o = 16; o; o >>= 1) s += __shfl_xor_sync(0xffffffffu, s, o);
    if (lane == 0) sred[warp] = s;
    __syncthreads();
    if (warp == 0) {
        float t = (lane < 8) ? sred[lane] : 0.f;
#pragma unroll
        for (int o = 4; o; o >>= 1) t += __shfl_xor_sync(0xffffffffu, t, o);
        if (lane == 0) sred[0] = t;
    }
    __syncthreads();
    float inv = 1.0f / sred[0];

    uint2 w;
    *(__half2*)&w.x = __floats2half2_rn(e0 * inv, e1 * inv);
    *(__half2*)&w.y = __floats2half2_rn(e2 * inv, e3 * inv);
    p[tid] = w;
}

// ---------------------------------------------------------------------------
extern "C" void kernel_launch(void* const* d_in, const int* in_sizes, int n_in,
                              void* d_out, int out_size) {
    (void)in_sizes; (void)n_in; (void)out_size;
    const float* inputs = (const float*)d_in[0];
    const float* gamma  = (const float*)d_in[1];
    const float* beta   = (const float*)d_in[2];
    const float* Wqkv   = (const float*)d_in[3];
    const float* bqkv   = (const float*)d_in[4];
    const float* Wout   = (const float*)d_in[5];
    const float* bout   = (const float*)d_in[6];
    float* out = (float*)d_out;

    f2h_wqkv<<<(C * NQKV + 255) / 256, 256>>>(Wqkv);
    f2h_wout<<<(C * C + 255) / 256, 256>>>(Wout);
    groupnorm_kernel<<<BNUM * G, 256>>>(inputs, gamma, beta);

    gemm_mma<0><<<dim3(NQKV / 128, MTOT / 128, 1), 256>>>(bqkv, nullptr, nullptr);
    gemm_mma<1><<<dim3(HW / 128, HW / 128, BNUM), 256>>>(nullptr, nullptr, nullptr);
    softmax_h<<<BNUM * HW, 256>>>();
    gemm_mma<2><<<dim3(C / 128, HW / 128, BNUM), 256>>>(nullptr, nullptr, nullptr);
    gemm_mma<3><<<dim3(C / 128, MTOT / 128, 1), 256>>>(bout, inputs, out);
}

// round 5
// speedup vs baseline: 4.5892x; 1.2377x over previous
#include <cuda_runtime.h>
#include <cuda_fp16.h>
#include <cstdint>
#include <cstddef>
#include <math.h>

#define BNUM 16
#define HW   1024
#define C    512
#define G    32
#define CG   16
#define NQKV 1536
#define MTOT (BNUM * HW)
#define SCALE 0.044194173824159216f   // 512^-0.5

// fp16 scratch (static device arrays: allowed)
__device__ __half g_xh[MTOT * C];
__device__ __half g_qh[MTOT * C];
__device__ __half g_kh[MTOT * C];
__device__ __half g_vh[MTOT * C];
__device__ __half g_sh[(size_t)BNUM * HW * HW];
__device__ __half g_oh[MTOT * C];
__device__ __half g_wqkvh[C * NQKV];
__device__ __half g_wouth[C * C];

// ---------------------------------------------------------------------------
// helpers
// ---------------------------------------------------------------------------
__device__ __forceinline__ uint32_t smaddr(const void* p) {
    return (uint32_t)__cvta_generic_to_shared(p);
}
__device__ __forceinline__ void ldsm4(uint32_t a, uint32_t& r0, uint32_t& r1,
                                      uint32_t& r2, uint32_t& r3) {
    asm volatile("ldmatrix.sync.aligned.m8n8.x4.shared.b16 {%0,%1,%2,%3},[%4];"
                 : "=r"(r0), "=r"(r1), "=r"(r2), "=r"(r3) : "r"(a));
}
__device__ __forceinline__ void ldsm4t(uint32_t a, uint32_t& r0, uint32_t& r1,
                                       uint32_t& r2, uint32_t& r3) {
    asm volatile("ldmatrix.sync.aligned.m8n8.x4.trans.shared.b16 {%0,%1,%2,%3},[%4];"
                 : "=r"(r0), "=r"(r1), "=r"(r2), "=r"(r3) : "r"(a));
}
__device__ __forceinline__ void mma16816(float* d, const uint32_t* a, const uint32_t* b) {
    asm volatile(
        "mma.sync.aligned.m16n8k16.row.col.f32.f16.f16.f32 "
        "{%0,%1,%2,%3},{%4,%5,%6,%7},{%8,%9},{%0,%1,%2,%3};"
        : "+f"(d[0]), "+f"(d[1]), "+f"(d[2]), "+f"(d[3])
        : "r"(a[0]), "r"(a[1]), "r"(a[2]), "r"(a[3]), "r"(b[0]), "r"(b[1]));
}
#define CPA16(dst, src) \
    asm volatile("cp.async.cg.shared.global [%0],[%1],16;" ::"r"(dst), "l"(src))
#define CPCOMMIT() asm volatile("cp.async.commit_group;")
#define CPWAIT0()  asm volatile("cp.async.wait_group 0;")
#define CPWAIT1()  asm volatile("cp.async.wait_group 1;")

// ---------------------------------------------------------------------------
// weight fp32 -> fp16 converters
// ---------------------------------------------------------------------------
__global__ void f2h_wqkv(const float* __restrict__ s) {
    int i = blockIdx.x * 256 + threadIdx.x;
    if (i < C * NQKV) g_wqkvh[i] = __float2half_rn(s[i]);
}
__global__ void f2h_wout(const float* __restrict__ s) {
    int i = blockIdx.x * 256 + threadIdx.x;
    if (i < C * C) g_wouth[i] = __float2half_rn(s[i]);
}

// ---------------------------------------------------------------------------
// GroupNorm -> fp16 g_xh
// ---------------------------------------------------------------------------
__global__ void groupnorm_kernel(const float* __restrict__ in,
                                 const float* __restrict__ gamma,
                                 const float* __restrict__ beta) {
    int b = blockIdx.x >> 5;
    int g = blockIdx.x & 31;
    int tid = threadIdx.x;
    const float* base = in + (size_t)b * HW * C + g * CG;
    float s = 0.f, ss = 0.f;
    for (int e = tid; e < HW * CG; e += 256) {
        int pos = e >> 4, c = e & 15;
        float v = base[(size_t)pos * C + c];
        s += v; ss += v * v;
    }
    __shared__ float rs[256], rss[256];
    rs[tid] = s; rss[tid] = ss;
    __syncthreads();
    for (int o = 128; o > 0; o >>= 1) {
        if (tid < o) { rs[tid] += rs[tid + o]; rss[tid] += rss[tid + o]; }
        __syncthreads();
    }
    const float invN = 1.0f / (HW * CG);
    float mean = rs[0] * invN;
    float var  = rss[0] * invN - mean * mean;
    float rstd = rsqrtf(var + 1e-3f);
    __half* outb = g_xh + (size_t)b * HW * C + g * CG;
    for (int e = tid; e < HW * CG; e += 256) {
        int pos = e >> 4, c = e & 15;
        float v = base[(size_t)pos * C + c];
        outb[(size_t)pos * C + c] =
            __float2half_rn((v - mean) * rstd * gamma[g * CG + c] + beta[g * CG + c]);
    }
}

// ---------------------------------------------------------------------------
// Unified fp16 tensor-core GEMM (mma.sync), 3-stage cp.async pipeline,
// 2 CTAs/SM via launch_bounds(256,2).
// EPI 0: g_xh[16384x512] @ g_wqkvh[512x1536]  -> scatter q/k/v (q scaled)
// EPI 1: Q @ K^T per batch (NT), store fp16 scores
// EPI 2: P @ V per batch (NN), store fp16 O
// EPI 3: O @ W_out + bias + residual -> fp32 out
// ---------------------------------------------------------------------------
template <int EPI>
__global__ void __launch_bounds__(256, 2)
gemm_mma(const float* __restrict__ bias,
         const float* __restrict__ resid,
         float* __restrict__ outF) {
    constexpr bool NT  = (EPI == 1);
    constexpr int  K   = (EPI == 2) ? 1024 : 512;
    constexpr int  KT  = K / 32;
    constexpr int  LDA = (EPI == 2) ? 1024 : 512;
    constexpr int  LDB = (EPI == 0) ? 1536 : 512;

    // dynamic smem: 3 stages of A [128][40], then 3 stages of B
    constexpr int ASTG = 128 * 40;                    // halfs per A stage
    constexpr int BROWS = NT ? 128 : 32;
    constexpr int BLDS  = NT ? 40 : 136;
    constexpr int BSTG  = BROWS * BLDS;
    extern __shared__ __half sm[];
    __half* Abuf = sm;
    __half* Bbuf = sm + 3 * ASTG;

    int tid = threadIdx.x, lane = tid & 31, warp = tid >> 5;
    int wm = warp & 3, wn = warp >> 2;
    int z = blockIdx.z;
    int m0 = blockIdx.y * 128, n0 = blockIdx.x * 128;

    const __half* A;
    const __half* B;
    if constexpr (EPI == 0)      { A = g_xh;                          B = g_wqkvh; }
    else if constexpr (EPI == 1) { A = g_qh + (size_t)z * HW * C;     B = g_kh + (size_t)z * HW * C; }
    else if constexpr (EPI == 2) { A = g_sh + (size_t)z * HW * HW;    B = g_vh + (size_t)z * HW * C; }
    else                         { A = g_oh;                          B = g_wouth; }

    float acc[2][8][4] = {};

    auto load = [&](int kt, int st) {
        int k0 = kt * 32;
        __half* As = Abuf + st * ASTG;
        __half* Bs = Bbuf + st * BSTG;
#pragma unroll
        for (int i = 0; i < 2; i++) {
            int c = tid + i * 256;
            int r = c >> 2, col = (c & 3) * 8;
            CPA16(smaddr(As + r * 40 + col), A + (size_t)(m0 + r) * LDA + k0 + col);
        }
        if constexpr (NT) {
#pragma unroll
            for (int i = 0; i < 2; i++) {
                int c = tid + i * 256;
                int r = c >> 2, col = (c & 3) * 8;
                CPA16(smaddr(Bs + r * 40 + col), B + (size_t)(n0 + r) * LDB + k0 + col);
            }
        } else {
#pragma unroll
            for (int i = 0; i < 2; i++) {
                int c = tid + i * 256;
                int r = c >> 4, col = (c & 15) * 8;
                CPA16(smaddr(Bs + r * 136 + col), B + (size_t)(k0 + r) * LDB + n0 + col);
            }
        }
        CPCOMMIT();
    };

    load(0, 0);
    load(1, 1);

    for (int kt = 0; kt < KT; kt++) {
        if (kt + 1 < KT) { CPWAIT1(); } else { CPWAIT0(); }
        __syncthreads();
        if (kt + 2 < KT) load(kt + 2, (kt + 2) % 3);
        int st = kt % 3;
        __half* As = Abuf + st * ASTG;
        __half* Bs = Bbuf + st * BSTG;
#pragma unroll
        for (int ks = 0; ks < 32; ks += 16) {
            uint32_t a[2][4], b[8][2];
#pragma unroll
            for (int mt = 0; mt < 2; mt++) {
                int r = wm * 32 + mt * 16 + (lane & 15);
                int col = ks + ((lane >> 4) << 3);
                ldsm4(smaddr(As + r * 40 + col), a[mt][0], a[mt][1], a[mt][2], a[mt][3]);
            }
            if constexpr (NT) {
#pragma unroll
                for (int ng = 0; ng < 4; ng++) {
                    int r = wn * 64 + ng * 16 + (lane & 15);
                    int col = ks + ((lane >> 4) << 3);
                    uint32_t r0, r1, r2, r3;
                    ldsm4(smaddr(Bs + r * 40 + col), r0, r1, r2, r3);
                    b[2 * ng][0] = r0; b[2 * ng][1] = r2;
                    b[2 * ng + 1][0] = r1; b[2 * ng + 1][1] = r3;
                }
            } else {
#pragma unroll
                for (int ng = 0; ng < 4; ng++) {
                    int r = ks + (lane & 15);
                    int col = wn * 64 + ng * 16 + ((lane >> 4) << 3);
                    uint32_t r0, r1, r2, r3;
                    ldsm4t(smaddr(Bs + r * 136 + col), r0, r1, r2, r3);
                    b[2 * ng][0] = r0; b[2 * ng][1] = r1;
                    b[2 * ng + 1][0] = r2; b[2 * ng + 1][1] = r3;
                }
            }
#pragma unroll
            for (int mt = 0; mt < 2; mt++)
#pragma unroll
                for (int nt = 0; nt < 8; nt++) mma16816(acc[mt][nt], a[mt], b[nt]);
        }
        __syncthreads();
    }

    // epilogue
#pragma unroll
    for (int mt = 0; mt < 2; mt++) {
#pragma unroll
        for (int nt = 0; nt < 8; nt++) {
            int r  = m0 + wm * 32 + mt * 16 + (lane >> 2);
            int cc = n0 + wn * 64 + nt * 8 + (lane & 3) * 2;
            float* v = acc[mt][nt];
            if constexpr (EPI == 0) {
#pragma unroll
                for (int h = 0; h < 2; h++) {
                    int rr = r + h * 8;
#pragma unroll
                    for (int j = 0; j < 2; j++) {
                        int n = cc + j;
                        float val = v[h * 2 + j] + bias[n];
                        int e = n % 3, ch = n / 3;
                        __half hv = __float2half_rn(e == 0 ? val * SCALE : val);
                        __half* dst = (e == 0) ? g_qh : ((e == 1) ? g_kh : g_vh);
                        dst[(size_t)rr * C + ch] = hv;
                    }
                }
            } else if constexpr (EPI == 1) {
                size_t base = (size_t)z * HW * HW;
                *(__half2*)&g_sh[base + (size_t)r * HW + cc] =
                    __floats2half2_rn(v[0], v[1]);
                *(__half2*)&g_sh[base + (size_t)(r + 8) * HW + cc] =
                    __floats2half2_rn(v[2], v[3]);
            } else if constexpr (EPI == 2) {
                size_t base = (size_t)z * HW * C;
                *(__half2*)&g_oh[base + (size_t)r * C + cc] =
                    __floats2half2_rn(v[0], v[1]);
                *(__half2*)&g_oh[base + (size_t)(r + 8) * C + cc] =
                    __floats2half2_rn(v[2], v[3]);
            } else {
                outF[(size_t)r * C + cc]     = v[0] + bias[cc]     + resid[(size_t)r * C + cc];
                outF[(size_t)r * C + cc + 1] = v[1] + bias[cc + 1] + resid[(size_t)r * C + cc + 1];
                outF[(size_t)(r + 8) * C + cc]     = v[2] + bias[cc]     + resid[(size_t)(r + 8) * C + cc];
                outF[(size_t)(r + 8) * C + cc + 1] = v[3] + bias[cc + 1] + resid[(size_t)(r + 8) * C + cc + 1];
            }
        }
    }
}

// ---------------------------------------------------------------------------
// fp16 in-place row softmax over 1024 cols (scale folded into Q)
// ---------------------------------------------------------------------------
__global__ void softmax_h() {
    size_t row = blockIdx.x;
    uint2* p = (uint2*)(g_sh + row * HW);
    int tid = threadIdx.x, lane = tid & 31, warp = tid >> 5;
    uint2 raw = p[tid];
    __half2 h0 = *(__half2*)&raw.x, h1 = *(__half2*)&raw.y;
    float2 f0 = __half22float2(h0), f1 = __half22float2(h1);

    float m = fmaxf(fmaxf(f0.x, f0.y), fmaxf(f1.x, f1.y));
#pragma unroll
    for (int o = 16; o; o >>= 1) m = fmaxf(m, __shfl_xor_sync(0xffffffffu, m, o));
    __shared__ float sred[8];
    if (lane == 0) sred[warp] = m;
    __syncthreads();
    if (warp == 0) {
        float t = (lane < 8) ? sred[lane] : -1e30f;
#pragma unroll
        for (int o = 4; o; o >>= 1) t = fmaxf(t, __shfl_xor_sync(0xffffffffu, t, o));
        if (lane == 0) sred[0] = t;
    }
    __syncthreads();
    float mf = sred[0];
    __syncthreads();

    float e0 = __expf(f0.x - mf), e1 = __expf(f0.y - mf);
    float e2 = __expf(f1.x - mf), e3 = __expf(f1.y - mf);
    float s = e0 + e1 + e2 + e3;
#pragma unroll
    for (int o = 16; o; o >>= 1) s += __shfl_xor_sync(0xffffffffu, s, o);
    if (lane == 0) sred[warp] = s;
    __syncthreads();
    if (warp == 0) {
        float t = (lane < 8) ? sred[lane] : 0.f;
#pragma unroll
        for (int o = 4; o; o >>= 1) t += __shfl_xor_sync(0xffffffffu, t, o);
        if (lane == 0) sred[0] = t;
    }
    __syncthreads();
    float inv = 1.0f / sred[0];

    uint2 w;
    *(__half2*)&w.x = __floats2half2_rn(e0 * inv, e1 * inv);
    *(__half2*)&w.y = __floats2half2_rn(e2 * inv, e3 * inv);
    p[tid] = w;
}

// ---------------------------------------------------------------------------
extern "C" void kernel_launch(void* const* d_in, const int* in_sizes, int n_in,
                              void* d_out, int out_size) {
    (void)in_sizes; (void)n_in; (void)out_size;
    const float* inputs = (const float*)d_in[0];
    const float* gamma  = (const float*)d_in[1];
    const float* beta   = (const float*)d_in[2];
    const float* Wqkv   = (const float*)d_in[3];
    const float* bqkv   = (const float*)d_in[4];
    const float* Wout   = (const float*)d_in[5];
    const float* bout   = (const float*)d_in[6];
    float* out = (float*)d_out;

    // dynamic smem sizes (bytes): 3*A + 3*B stages of fp16
    const int smNT = (3 * 128 * 40 + 3 * 128 * 40) * 2;   // 61440
    const int smNN = (3 * 128 * 40 + 3 * 32 * 136) * 2;   // 56832
    cudaFuncSetAttribute(gemm_mma<0>, cudaFuncAttributeMaxDynamicSharedMemorySize, smNN);
    cudaFuncSetAttribute(gemm_mma<1>, cudaFuncAttributeMaxDynamicSharedMemorySize, smNT);
    cudaFuncSetAttribute(gemm_mma<2>, cudaFuncAttributeMaxDynamicSharedMemorySize, smNN);
    cudaFuncSetAttribute(gemm_mma<3>, cudaFuncAttributeMaxDynamicSharedMemorySize, smNN);

    f2h_wqkv<<<(C * NQKV + 255) / 256, 256>>>(Wqkv);
    f2h_wout<<<(C * C + 255) / 256, 256>>>(Wout);
    groupnorm_kernel<<<BNUM * G, 256>>>(inputs, gamma, beta);

    gemm_mma<0><<<dim3(NQKV / 128, MTOT / 128, 1), 256, smNN>>>(bqkv, nullptr, nullptr);
    gemm_mma<1><<<dim3(HW / 128, HW / 128, BNUM), 256, smNT>>>(nullptr, nullptr, nullptr);
    softmax_h<<<BNUM * HW, 256>>>();
    gemm_mma<2><<<dim3(C / 128, HW / 128, BNUM), 256, smNN>>>(nullptr, nullptr, nullptr);
    gemm_mma<3><<<dim3(C / 128, MTOT / 128, 1), 256, smNN>>>(bout, inputs, out);
}

// round 6
// speedup vs baseline: 4.8200x; 1.0503x over previous
#include <cuda_runtime.h>
#include <cuda_fp16.h>
#include <cstdint>
#include <cstddef>
#include <math.h>

#define BNUM 16
#define HW   1024
#define C    512
#define G    32
#define CG   16
#define NQKV 1536
#define MTOT (BNUM * HW)
#define SCALE 0.044194173824159216f   // 512^-0.5

// fp16 scratch (static device arrays: allowed)
__device__ __half g_xh[MTOT * C];
__device__ __half g_qh[MTOT * C];
__device__ __half g_kh[MTOT * C];
__device__ __half g_vh[MTOT * C];
__device__ __half g_sh[(size_t)BNUM * HW * HW];
__device__ __half g_oh[MTOT * C];
__device__ __half g_wqkvh[C * NQKV];
__device__ __half g_wouth[C * C];

// ---------------------------------------------------------------------------
// helpers
// ---------------------------------------------------------------------------
__device__ __forceinline__ uint32_t smaddr(const void* p) {
    return (uint32_t)__cvta_generic_to_shared(p);
}
__device__ __forceinline__ void ldsm4(uint32_t a, uint32_t& r0, uint32_t& r1,
                                      uint32_t& r2, uint32_t& r3) {
    asm volatile("ldmatrix.sync.aligned.m8n8.x4.shared.b16 {%0,%1,%2,%3},[%4];"
                 : "=r"(r0), "=r"(r1), "=r"(r2), "=r"(r3) : "r"(a));
}
__device__ __forceinline__ void ldsm4t(uint32_t a, uint32_t& r0, uint32_t& r1,
                                       uint32_t& r2, uint32_t& r3) {
    asm volatile("ldmatrix.sync.aligned.m8n8.x4.trans.shared.b16 {%0,%1,%2,%3},[%4];"
                 : "=r"(r0), "=r"(r1), "=r"(r2), "=r"(r3) : "r"(a));
}
__device__ __forceinline__ void mma16816(float* d, const uint32_t* a, const uint32_t* b) {
    asm volatile(
        "mma.sync.aligned.m16n8k16.row.col.f32.f16.f16.f32 "
        "{%0,%1,%2,%3},{%4,%5,%6,%7},{%8,%9},{%0,%1,%2,%3};"
        : "+f"(d[0]), "+f"(d[1]), "+f"(d[2]), "+f"(d[3])
        : "r"(a[0]), "r"(a[1]), "r"(a[2]), "r"(a[3]), "r"(b[0]), "r"(b[1]));
}
#define CPA16(dst, src) \
    asm volatile("cp.async.cg.shared.global [%0],[%1],16;" ::"r"(dst), "l"(src))
#define CPCOMMIT() asm volatile("cp.async.commit_group;")
#define CPWAIT0()  asm volatile("cp.async.wait_group 0;")
#define CPWAIT1()  asm volatile("cp.async.wait_group 1;")

// ---------------------------------------------------------------------------
// weight fp32 -> fp16 converters
// ---------------------------------------------------------------------------
__global__ void f2h_wqkv(const float* __restrict__ s) {
    int i = blockIdx.x * 256 + threadIdx.x;
    if (i < C * NQKV) g_wqkvh[i] = __float2half_rn(s[i]);
}
__global__ void f2h_wout(const float* __restrict__ s) {
    int i = blockIdx.x * 256 + threadIdx.x;
    if (i < C * C) g_wouth[i] = __float2half_rn(s[i]);
}

// ---------------------------------------------------------------------------
// GroupNorm -> fp16 g_xh
// ---------------------------------------------------------------------------
__global__ void groupnorm_kernel(const float* __restrict__ in,
                                 const float* __restrict__ gamma,
                                 const float* __restrict__ beta) {
    int b = blockIdx.x >> 5;
    int g = blockIdx.x & 31;
    int tid = threadIdx.x;
    const float* base = in + (size_t)b * HW * C + g * CG;
    float s = 0.f, ss = 0.f;
    for (int e = tid; e < HW * CG; e += 256) {
        int pos = e >> 4, c = e & 15;
        float v = base[(size_t)pos * C + c];
        s += v; ss += v * v;
    }
    __shared__ float rs[256], rss[256];
    rs[tid] = s; rss[tid] = ss;
    __syncthreads();
    for (int o = 128; o > 0; o >>= 1) {
        if (tid < o) { rs[tid] += rs[tid + o]; rss[tid] += rss[tid + o]; }
        __syncthreads();
    }
    const float invN = 1.0f / (HW * CG);
    float mean = rs[0] * invN;
    float var  = rss[0] * invN - mean * mean;
    float rstd = rsqrtf(var + 1e-3f);
    __half* outb = g_xh + (size_t)b * HW * C + g * CG;
    for (int e = tid; e < HW * CG; e += 256) {
        int pos = e >> 4, c = e & 15;
        float v = base[(size_t)pos * C + c];
        outb[(size_t)pos * C + c] =
            __float2half_rn((v - mean) * rstd * gamma[g * CG + c] + beta[g * CG + c]);
    }
}

// ---------------------------------------------------------------------------
// fp16 mma.sync GEMM: 128-thread CTA, 4 warps (2x2), warp tile 64x64,
// block tile 128x128, BK=32, 3-stage cp.async, 2 CTAs/SM.
// EPI 0: X @ Wqkv -> scatter q/k/v (q scaled)
// EPI 1: Q @ K^T per batch (NT) -> fp16 scores
// EPI 2: P @ V per batch (NN)  -> fp16 O
// EPI 3: O @ W_out + bias + residual -> fp32 out
// ---------------------------------------------------------------------------
template <int EPI>
__global__ void __launch_bounds__(128, 2)
gemm_mma(const float* __restrict__ bias,
         const float* __restrict__ resid,
         float* __restrict__ outF) {
    constexpr bool NT  = (EPI == 1);
    constexpr int  K   = (EPI == 2) ? 1024 : 512;
    constexpr int  KT  = K / 32;
    constexpr int  LDA = (EPI == 2) ? 1024 : 512;
    constexpr int  LDB = (EPI == 0) ? 1536 : 512;

    constexpr int ASTG = 128 * 40;                  // halfs per A stage
    constexpr int BROWS = NT ? 128 : 32;
    constexpr int BLDS  = NT ? 40 : 136;
    constexpr int BSTG  = BROWS * BLDS;
    extern __shared__ __half sm[];
    __half* Abuf = sm;
    __half* Bbuf = sm + 3 * ASTG;

    int tid = threadIdx.x, lane = tid & 31, warp = tid >> 5;
    int wm = warp & 1, wn = warp >> 1;              // 2x2 warps, 64x64 tiles
    int z = blockIdx.z;
    int m0 = blockIdx.y * 128, n0 = blockIdx.x * 128;

    const __half* A;
    const __half* B;
    if constexpr (EPI == 0)      { A = g_xh;                          B = g_wqkvh; }
    else if constexpr (EPI == 1) { A = g_qh + (size_t)z * HW * C;     B = g_kh + (size_t)z * HW * C; }
    else if constexpr (EPI == 2) { A = g_sh + (size_t)z * HW * HW;    B = g_vh + (size_t)z * HW * C; }
    else                         { A = g_oh;                          B = g_wouth; }

    float acc[4][8][4] = {};

    auto load = [&](int kt, int st) {
        int k0 = kt * 32;
        __half* As = Abuf + st * ASTG;
        __half* Bs = Bbuf + st * BSTG;
#pragma unroll
        for (int i = 0; i < 4; i++) {               // A: 128 rows x 32 halfs
            int c = tid + i * 128;
            int r = c >> 2, col = (c & 3) * 8;
            CPA16(smaddr(As + r * 40 + col), A + (size_t)(m0 + r) * LDA + k0 + col);
        }
        if constexpr (NT) {
#pragma unroll
            for (int i = 0; i < 4; i++) {           // B: 128 rows(n) x 32 halfs(k)
                int c = tid + i * 128;
                int r = c >> 2, col = (c & 3) * 8;
                CPA16(smaddr(Bs + r * 40 + col), B + (size_t)(n0 + r) * LDB + k0 + col);
            }
        } else {
#pragma unroll
            for (int i = 0; i < 4; i++) {           // B: 32 rows(k) x 128 halfs(n)
                int c = tid + i * 128;
                int r = c >> 4, col = (c & 15) * 8;
                CPA16(smaddr(Bs + r * 136 + col), B + (size_t)(k0 + r) * LDB + n0 + col);
            }
        }
        CPCOMMIT();
    };

    load(0, 0);
    load(1, 1);

    for (int kt = 0; kt < KT; kt++) {
        if (kt + 1 < KT) { CPWAIT1(); } else { CPWAIT0(); }
        __syncthreads();
        if (kt + 2 < KT) load(kt + 2, (kt + 2) % 3);
        int st = kt % 3;
        __half* As = Abuf + st * ASTG;
        __half* Bs = Bbuf + st * BSTG;
#pragma unroll
        for (int ks = 0; ks < 32; ks += 16) {
            uint32_t a[4][4], b[8][2];
#pragma unroll
            for (int mt = 0; mt < 4; mt++) {        // 64 rows of A
                int r = wm * 64 + mt * 16 + (lane & 15);
                int col = ks + ((lane >> 4) << 3);
                ldsm4(smaddr(As + r * 40 + col), a[mt][0], a[mt][1], a[mt][2], a[mt][3]);
            }
            if constexpr (NT) {
#pragma unroll
                for (int ng = 0; ng < 4; ng++) {    // 64 cols of B
                    int r = wn * 64 + ng * 16 + (lane & 15);
                    int col = ks + ((lane >> 4) << 3);
                    uint32_t r0, r1, r2, r3;
                    ldsm4(smaddr(Bs + r * 40 + col), r0, r1, r2, r3);
                    b[2 * ng][0] = r0; b[2 * ng][1] = r2;
                    b[2 * ng + 1][0] = r1; b[2 * ng + 1][1] = r3;
                }
            } else {
#pragma unroll
                for (int ng = 0; ng < 4; ng++) {
                    int r = ks + (lane & 15);
                    int col = wn * 64 + ng * 16 + ((lane >> 4) << 3);
                    uint32_t r0, r1, r2, r3;
                    ldsm4t(smaddr(Bs + r * 136 + col), r0, r1, r2, r3);
                    b[2 * ng][0] = r0; b[2 * ng][1] = r1;
                    b[2 * ng + 1][0] = r2; b[2 * ng + 1][1] = r3;
                }
            }
#pragma unroll
            for (int mt = 0; mt < 4; mt++)
#pragma unroll
                for (int nt = 0; nt < 8; nt++) mma16816(acc[mt][nt], a[mt], b[nt]);
        }
        __syncthreads();
    }

    // epilogue
#pragma unroll
    for (int mt = 0; mt < 4; mt++) {
#pragma unroll
        for (int nt = 0; nt < 8; nt++) {
            int r  = m0 + wm * 64 + mt * 16 + (lane >> 2);
            int cc = n0 + wn * 64 + nt * 8 + (lane & 3) * 2;
            float* v = acc[mt][nt];
            if constexpr (EPI == 0) {
#pragma unroll
                for (int h = 0; h < 2; h++) {
                    int rr = r + h * 8;
#pragma unroll
                    for (int j = 0; j < 2; j++) {
                        int n = cc + j;
                        float val = v[h * 2 + j] + bias[n];
                        int e = n % 3, ch = n / 3;
                        __half hv = __float2half_rn(e == 0 ? val * SCALE : val);
                        __half* dst = (e == 0) ? g_qh : ((e == 1) ? g_kh : g_vh);
                        dst[(size_t)rr * C + ch] = hv;
                    }
                }
            } else if constexpr (EPI == 1) {
                size_t base = (size_t)z * HW * HW;
                *(__half2*)&g_sh[base + (size_t)r * HW + cc] =
                    __floats2half2_rn(v[0], v[1]);
                *(__half2*)&g_sh[base + (size_t)(r + 8) * HW + cc] =
                    __floats2half2_rn(v[2], v[3]);
            } else if constexpr (EPI == 2) {
                size_t base = (size_t)z * HW * C;
                *(__half2*)&g_oh[base + (size_t)r * C + cc] =
                    __floats2half2_rn(v[0], v[1]);
                *(__half2*)&g_oh[base + (size_t)(r + 8) * C + cc] =
                    __floats2half2_rn(v[2], v[3]);
            } else {
                outF[(size_t)r * C + cc]     = v[0] + bias[cc]     + resid[(size_t)r * C + cc];
                outF[(size_t)r * C + cc + 1] = v[1] + bias[cc + 1] + resid[(size_t)r * C + cc + 1];
                outF[(size_t)(r + 8) * C + cc]     = v[2] + bias[cc]     + resid[(size_t)(r + 8) * C + cc];
                outF[(size_t)(r + 8) * C + cc + 1] = v[3] + bias[cc + 1] + resid[(size_t)(r + 8) * C + cc + 1];
            }
        }
    }
}

// ---------------------------------------------------------------------------
// fp16 in-place row softmax over 1024 cols (scale folded into Q)
// ---------------------------------------------------------------------------
__global__ void softmax_h() {
    size_t row = blockIdx.x;
    uint2* p = (uint2*)(g_sh + row * HW);
    int tid = threadIdx.x, lane = tid & 31, warp = tid >> 5;
    uint2 raw = p[tid];
    __half2 h0 = *(__half2*)&raw.x, h1 = *(__half2*)&raw.y;
    float2 f0 = __half22float2(h0), f1 = __half22float2(h1);

    float m = fmaxf(fmaxf(f0.x, f0.y), fmaxf(f1.x, f1.y));
#pragma unroll
    for (int o = 16; o; o >>= 1) m = fmaxf(m, __shfl_xor_sync(0xffffffffu, m, o));
    __shared__ float sred[8];
    if (lane == 0) sred[warp] = m;
    __syncthreads();
    if (warp == 0) {
        float t = (lane < 8) ? sred[lane] : -1e30f;
#pragma unroll
        for (int o = 4; o; o >>= 1) t = fmaxf(t, __shfl_xor_sync(0xffffffffu, t, o));
        if (lane == 0) sred[0] = t;
    }
    __syncthreads();
    float mf = sred[0];
    __syncthreads();

    float e0 = __expf(f0.x - mf), e1 = __expf(f0.y - mf);
    float e2 = __expf(f1.x - mf), e3 = __expf(f1.y - mf);
    float s = e0 + e1 + e2 + e3;
#pragma unroll
    for (int o = 16; o; o >>= 1) s += __shfl_xor_sync(0xffffffffu, s, o);
    if (lane == 0) sred[warp] = s;
    __syncthreads();
    if (warp == 0) {
        float t = (lane < 8) ? sred[lane] : 0.f;
#pragma unroll
        for (int o = 4; o; o >>= 1) t += __shfl_xor_sync(0xffffffffu, t, o);
        if (lane == 0) sred[0] = t;
    }
    __syncthreads();
    float inv = 1.0f / sred[0];

    uint2 w;
    *(__half2*)&w.x = __floats2half2_rn(e0 * inv, e1 * inv);
    *(__half2*)&w.y = __floats2half2_rn(e2 * inv, e3 * inv);
    p[tid] = w;
}

// ---------------------------------------------------------------------------
extern "C" void kernel_launch(void* const* d_in, const int* in_sizes, int n_in,
                              void* d_out, int out_size) {
    (void)in_sizes; (void)n_in; (void)out_size;
    const float* inputs = (const float*)d_in[0];
    const float* gamma  = (const float*)d_in[1];
    const float* beta   = (const float*)d_in[2];
    const float* Wqkv   = (const float*)d_in[3];
    const float* bqkv   = (const float*)d_in[4];
    const float* Wout   = (const float*)d_in[5];
    const float* bout   = (const float*)d_in[6];
    float* out = (float*)d_out;

    const int smNT = (3 * 128 * 40 + 3 * 128 * 40) * 2;   // 61440
    const int smNN = (3 * 128 * 40 + 3 * 32 * 136) * 2;   // 56832
    cudaFuncSetAttribute(gemm_mma<0>, cudaFuncAttributeMaxDynamicSharedMemorySize, smNN);
    cudaFuncSetAttribute(gemm_mma<1>, cudaFuncAttributeMaxDynamicSharedMemorySize, smNT);
    cudaFuncSetAttribute(gemm_mma<2>, cudaFuncAttributeMaxDynamicSharedMemorySize, smNN);
    cudaFuncSetAttribute(gemm_mma<3>, cudaFuncAttributeMaxDynamicSharedMemorySize, smNN);

    f2h_wqkv<<<(C * NQKV + 255) / 256, 256>>>(Wqkv);
    f2h_wout<<<(C * C + 255) / 256, 256>>>(Wout);
    groupnorm_kernel<<<BNUM * G, 256>>>(inputs, gamma, beta);

    gemm_mma<0><<<dim3(NQKV / 128, MTOT / 128, 1), 128, smNN>>>(bqkv, nullptr, nullptr);
    gemm_mma<1><<<dim3(HW / 128, HW / 128, BNUM), 128, smNT>>>(nullptr, nullptr, nullptr);
    softmax_h<<<BNUM * HW, 256>>>();
    gemm_mma<2><<<dim3(C / 128, HW / 128, BNUM), 128, smNN>>>(nullptr, nullptr, nullptr);
    gemm_mma<3><<<dim3(C / 128, MTOT / 128, 1), 128, smNN>>>(bout, inputs, out);
}

// round 8
// speedup vs baseline: 7.1427x; 1.4819x over previous
#include <cuda_runtime.h>
#include <cuda_fp16.h>
#include <cstdint>
#include <cstddef>
#include <math.h>

#define BNUM 16
#define HW   1024
#define C    512
#define G    32
#define CG   16
#define NQKV 1536
#define MTOT (BNUM * HW)
#define SCALE 0.044194173824159216f   // 512^-0.5

// fp16 scratch
__device__ __half g_xh[MTOT * C];
__device__ __half g_qh[MTOT * C];
__device__ __half g_kh[MTOT * C];
__device__ __half g_vh[MTOT * C];
__device__ __half g_sh[(size_t)BNUM * HW * HW];
__device__ __half g_oh[MTOT * C];
__device__ __half g_wqkvh[NQKV * C];   // permuted: [n'=e*512+ch][k], q-scale folded
__device__ __half g_wouth[C * C];
__device__ float  g_bqr[NQKV];         // permuted (scaled) qkv bias

// ---------------------------------------------------------------------------
// helpers
// ---------------------------------------------------------------------------
__device__ __forceinline__ uint32_t smaddr(const void* p) {
    return (uint32_t)__cvta_generic_to_shared(p);
}
__device__ __forceinline__ uint32_t swz(uint32_t off) {       // SW128 for 128B rows
    return off ^ ((off >> 3) & 0x70);
}
__device__ __forceinline__ void ldsm4(uint32_t a, uint32_t& r0, uint32_t& r1,
                                      uint32_t& r2, uint32_t& r3) {
    asm volatile("ldmatrix.sync.aligned.m8n8.x4.shared.b16 {%0,%1,%2,%3},[%4];"
                 : "=r"(r0), "=r"(r1), "=r"(r2), "=r"(r3) : "r"(a));
}
__device__ __forceinline__ void ldsm4t(uint32_t a, uint32_t& r0, uint32_t& r1,
                                       uint32_t& r2, uint32_t& r3) {
    asm volatile("ldmatrix.sync.aligned.m8n8.x4.trans.shared.b16 {%0,%1,%2,%3},[%4];"
                 : "=r"(r0), "=r"(r1), "=r"(r2), "=r"(r3) : "r"(a));
}
__device__ __forceinline__ void mma16816(float* d, const uint32_t* a, const uint32_t* b) {
    asm volatile(
        "mma.sync.aligned.m16n8k16.row.col.f32.f16.f16.f32 "
        "{%0,%1,%2,%3},{%4,%5,%6,%7},{%8,%9},{%0,%1,%2,%3};"
        : "+f"(d[0]), "+f"(d[1]), "+f"(d[2]), "+f"(d[3])
        : "r"(a[0]), "r"(a[1]), "r"(a[2]), "r"(a[3]), "r"(b[0]), "r"(b[1]));
}
#define CPA16(dst, src) \
    asm volatile("cp.async.cg.shared.global [%0],[%1],16;" ::"r"(dst), "l"(src))
#define CPCOMMIT() asm volatile("cp.async.commit_group;")
#define CPWAIT0()  asm volatile("cp.async.wait_group 0;")
#define CPWAIT1()  asm volatile("cp.async.wait_group 1;")

// ---------------------------------------------------------------------------
// weight converters (QKV permuted to [n'][k] + scale/bias folded)
// ---------------------------------------------------------------------------
__global__ void conv_wqkv(const float* __restrict__ W, const float* __restrict__ bq) {
    int idx = blockIdx.x * 256 + threadIdx.x;
    if (idx >= NQKV * C) return;
    int np = idx >> 9;          // n' = e*512 + ch
    int k  = idx & 511;
    int e  = np >> 9;
    int ch = np & 511;
    float s = (e == 0) ? SCALE : 1.0f;
    g_wqkvh[idx] = __float2half_rn(W[(size_t)k * NQKV + ch * 3 + e] * s);
    if (k == 0) g_bqr[np] = bq[ch * 3 + e] * s;
}
__global__ void f2h_wout(const float* __restrict__ s) {
    int i = blockIdx.x * 256 + threadIdx.x;
    if (i < C * C) g_wouth[i] = __float2half_rn(s[i]);
}

// ---------------------------------------------------------------------------
// GroupNorm -> fp16 g_xh
// ---------------------------------------------------------------------------
__global__ void groupnorm_kernel(const float* __restrict__ in,
                                 const float* __restrict__ gamma,
                                 const float* __restrict__ beta) {
    int b = blockIdx.x >> 5;
    int g = blockIdx.x & 31;
    int tid = threadIdx.x;
    const float* base = in + (size_t)b * HW * C + g * CG;
    float s = 0.f, ss = 0.f;
    for (int e = tid; e < HW * CG; e += 256) {
        int pos = e >> 4, c = e & 15;
        float v = base[(size_t)pos * C + c];
        s += v; ss += v * v;
    }
    __shared__ float rs[256], rss[256];
    rs[tid] = s; rss[tid] = ss;
    __syncthreads();
    for (int o = 128; o > 0; o >>= 1) {
        if (tid < o) { rs[tid] += rs[tid + o]; rss[tid] += rss[tid + o]; }
        __syncthreads();
    }
    const float invN = 1.0f / (HW * CG);
    float mean = rs[0] * invN;
    float var  = rss[0] * invN - mean * mean;
    float rstd = rsqrtf(var + 1e-3f);
    __half* outb = g_xh + (size_t)b * HW * C + g * CG;
    for (int e = tid; e < HW * CG; e += 256) {
        int pos = e >> 4, c = e & 15;
        float v = base[(size_t)pos * C + c];
        outb[(size_t)pos * C + c] =
            __float2half_rn((v - mean) * rstd * gamma[g * CG + c] + beta[g * CG + c]);
    }
}

// ---------------------------------------------------------------------------
// fp16 mma.sync GEMM: 128 thr (2x2 warps, 64x64 warp tile), block 128x128,
// BK=64, 3-stage cp.async (distance 2), 1 barrier/kt, frag ping-pong,
// SW128-swizzled A (and NT B), 2 CTAs/SM.
// EPI 0: X @ Wqkv' (NT: weights are [n'][k]) -> q/k/v (bias folded)
// EPI 1: Q @ K^T (NT, per batch) -> fp16 scores
// EPI 2: P @ V  (NN, per batch)  -> fp16 O
// EPI 3: O @ W_out + bias + residual -> fp32 out (NN)
// ---------------------------------------------------------------------------
template <int EPI>
__global__ void __launch_bounds__(128, 2)
gemm_mma(const float* __restrict__ bias,
         const float* __restrict__ resid,
         float* __restrict__ outF) {
    constexpr bool NT  = (EPI <= 1);               // FIX: EPI 0 weights are [n'][k]
    constexpr int  K   = (EPI == 2) ? 1024 : 512;
    constexpr int  KT  = K / 64;
    constexpr int  LDA = (EPI == 2) ? 1024 : 512;
    constexpr int  LDB = 512;

    constexpr int ASTG_B = 128 * 128;              // bytes per A stage (swizzled)
    constexpr int BSTG_B = NT ? (128 * 128) : (64 * 136 * 2);
    extern __shared__ char smc[];
    char* Abuf = smc;
    char* Bbuf = smc + 3 * ASTG_B;

    int tid = threadIdx.x, lane = tid & 31, warp = tid >> 5;
    int wm = warp & 1, wn = warp >> 1;             // 2x2 warps, 64x64 tiles
    int z = blockIdx.z;
    int m0 = blockIdx.y * 128, n0 = blockIdx.x * 128;

    const __half* A;
    const __half* B;
    if constexpr (EPI == 0)      { A = g_xh;                          B = g_wqkvh; }
    else if constexpr (EPI == 1) { A = g_qh + (size_t)z * HW * C;     B = g_kh + (size_t)z * HW * C; }
    else if constexpr (EPI == 2) { A = g_sh + (size_t)z * HW * HW;    B = g_vh + (size_t)z * HW * C; }
    else                         { A = g_oh;                          B = g_wouth; }

    float acc[4][8][4] = {};

    auto load = [&](int kt, int st) {
        int k0 = kt * 64;
        uint32_t Asm = smaddr(Abuf + st * ASTG_B);
        uint32_t Bsm = smaddr(Bbuf + st * BSTG_B);
#pragma unroll
        for (int i = 0; i < 8; i++) {              // A: 128 rows x 64 halfs, SW128
            int c = tid + i * 128;
            int r = c >> 3, ch = c & 7;            // 16B chunk index
            CPA16(Asm + swz((uint32_t)(r * 128 + ch * 16)),
                  A + (size_t)(m0 + r) * LDA + k0 + ch * 8);
        }
        if constexpr (NT) {
#pragma unroll
            for (int i = 0; i < 8; i++) {          // B: 128 rows(n) x 64 halfs, SW128
                int c = tid + i * 128;
                int r = c >> 3, ch = c & 7;
                CPA16(Bsm + swz((uint32_t)(r * 128 + ch * 16)),
                      B + (size_t)(n0 + r) * LDB + k0 + ch * 8);
            }
        } else {
#pragma unroll
            for (int i = 0; i < 8; i++) {          // B: 64 rows(k) x 128 halfs, pad 136
                int c = tid + i * 128;
                int r = c >> 4, ch = c & 15;
                CPA16(Bsm + (uint32_t)(r * 272 + ch * 16),
                      B + (size_t)(k0 + r) * LDB + n0 + ch * 8);
            }
        }
        CPCOMMIT();
    };

    // fragment loader for one k16 step
    auto ldfrag = [&](int st, int ks, uint32_t a[4][4], uint32_t b[8][2]) {
        uint32_t Asm = smaddr(Abuf + st * ASTG_B);
        uint32_t Bsm = smaddr(Bbuf + st * BSTG_B);
        int colh = ks + ((lane >> 4) << 3);        // half index, multiple of 8
#pragma unroll
        for (int mt = 0; mt < 4; mt++) {
            int r = wm * 64 + mt * 16 + (lane & 15);
            ldsm4(Asm + swz((uint32_t)(r * 128 + colh * 2)),
                  a[mt][0], a[mt][1], a[mt][2], a[mt][3]);
        }
        if constexpr (NT) {
#pragma unroll
            for (int ng = 0; ng < 4; ng++) {
                int r = wn * 64 + ng * 16 + (lane & 15);
                uint32_t r0, r1, r2, r3;
                ldsm4(Bsm + swz((uint32_t)(r * 128 + colh * 2)), r0, r1, r2, r3);
                b[2 * ng][0] = r0; b[2 * ng][1] = r2;
                b[2 * ng + 1][0] = r1; b[2 * ng + 1][1] = r3;
            }
        } else {
#pragma unroll
            for (int ng = 0; ng < 4; ng++) {
                int r = ks + (lane & 15);
                int col = wn * 64 + ng * 16 + ((lane >> 4) << 3);
                uint32_t r0, r1, r2, r3;
                ldsm4t(Bsm + (uint32_t)(r * 272 + col * 2), r0, r1, r2, r3);
                b[2 * ng][0] = r0; b[2 * ng][1] = r1;
                b[2 * ng + 1][0] = r2; b[2 * ng + 1][1] = r3;
            }
        }
    };

    auto mma_all = [&](uint32_t a[4][4], uint32_t b[8][2]) {
#pragma unroll
        for (int mt = 0; mt < 4; mt++)
#pragma unroll
            for (int nt = 0; nt < 8; nt++) mma16816(acc[mt][nt], a[mt], b[nt]);
    };

    load(0, 0);
    load(1, 1);

    for (int kt = 0; kt < KT; kt++) {
        if (kt + 1 < KT) { CPWAIT1(); } else { CPWAIT0(); }
        __syncthreads();
        if (kt + 2 < KT) load(kt + 2, (kt + 2) % 3);
        int st = kt % 3;
        uint32_t a0[4][4], b0[8][2], a1[4][4], b1[8][2];
        ldfrag(st, 0,  a0, b0);
        ldfrag(st, 16, a1, b1);
        mma_all(a0, b0);
        ldfrag(st, 32, a0, b0);
        mma_all(a1, b1);
        ldfrag(st, 48, a1, b1);
        mma_all(a0, b0);
        mma_all(a1, b1);
    }

    // epilogue
#pragma unroll
    for (int mt = 0; mt < 4; mt++) {
#pragma unroll
        for (int nt = 0; nt < 8; nt++) {
            int r  = m0 + wm * 64 + mt * 16 + (lane >> 2);
            int nl = wn * 64 + nt * 8 + (lane & 3) * 2;   // local col in [0,128)
            float* v = acc[mt][nt];
            if constexpr (EPI == 0) {
                int e = n0 >> 9;
                __half* dst = (e == 0) ? g_qh : ((e == 1) ? g_kh : g_vh);
                int ch = (n0 & 511) + nl;
                float b0f = g_bqr[n0 + nl], b1f = g_bqr[n0 + nl + 1];
                *(__half2*)&dst[(size_t)r * C + ch] =
                    __floats2half2_rn(v[0] + b0f, v[1] + b1f);
                *(__half2*)&dst[(size_t)(r + 8) * C + ch] =
                    __floats2half2_rn(v[2] + b0f, v[3] + b1f);
            } else if constexpr (EPI == 1) {
                size_t base = (size_t)z * HW * HW;
                int cc = n0 + nl;
                *(__half2*)&g_sh[base + (size_t)r * HW + cc] =
                    __floats2half2_rn(v[0], v[1]);
                *(__half2*)&g_sh[base + (size_t)(r + 8) * HW + cc] =
                    __floats2half2_rn(v[2], v[3]);
            } else if constexpr (EPI == 2) {
                size_t base = (size_t)z * HW * C;
                int cc = n0 + nl;
                *(__half2*)&g_oh[base + (size_t)r * C + cc] =
                    __floats2half2_rn(v[0], v[1]);
                *(__half2*)&g_oh[base + (size_t)(r + 8) * C + cc] =
                    __floats2half2_rn(v[2], v[3]);
            } else {
                int cc = n0 + nl;
                outF[(size_t)r * C + cc]     = v[0] + bias[cc]     + resid[(size_t)r * C + cc];
                outF[(size_t)r * C + cc + 1] = v[1] + bias[cc + 1] + resid[(size_t)r * C + cc + 1];
                outF[(size_t)(r + 8) * C + cc]     = v[2] + bias[cc]     + resid[(size_t)(r + 8) * C + cc];
                outF[(size_t)(r + 8) * C + cc + 1] = v[3] + bias[cc + 1] + resid[(size_t)(r + 8) * C + cc + 1];
            }
        }
    }
}

// ---------------------------------------------------------------------------
// fp16 in-place row softmax over 1024 cols (scale folded into Q path)
// ---------------------------------------------------------------------------
__global__ void softmax_h() {
    size_t row = blockIdx.x;
    uint2* p = (uint2*)(g_sh + row * HW);
    int tid = threadIdx.x, lane = tid & 31, warp = tid >> 5;
    uint2 raw = p[tid];
    __half2 h0 = *(__half2*)&raw.x, h1 = *(__half2*)&raw.y;
    float2 f0 = __half22float2(h0), f1 = __half22float2(h1);

    float m = fmaxf(fmaxf(f0.x, f0.y), fmaxf(f1.x, f1.y));
#pragma unroll
    for (int o = 16; o; o >>= 1) m = fmaxf(m, __shfl_xor_sync(0xffffffffu, m, o));
    __shared__ float sred[8];
    if (lane == 0) sred[warp] = m;
    __syncthreads();
    if (warp == 0) {
        float t = (lane < 8) ? sred[lane] : -1e30f;
#pragma unroll
        for (int o = 4; o; o >>= 1) t = fmaxf(t, __shfl_xor_sync(0xffffffffu, t, o));
        if (lane == 0) sred[0] = t;
    }
    __syncthreads();
    float mf = sred[0];
    __syncthreads();

    float e0 = __expf(f0.x - mf), e1 = __expf(f0.y - mf);
    float e2 = __expf(f1.x - mf), e3 = __expf(f1.y - mf);
    float s = e0 + e1 + e2 + e3;
#pragma unroll
    for (int o = 16; o; o >>= 1) s += __shfl_xor_sync(0xffffffffu, s, o);
    if (lane == 0) sred[warp] = s;
    __syncthreads();
    if (warp == 0) {
        float t = (lane < 8) ? sred[lane] : 0.f;
#pragma unroll
        for (int o = 4; o; o >>= 1) t += __shfl_xor_sync(0xffffffffu, t, o);
        if (lane == 0) sred[0] = t;
    }
    __syncthreads();
    float inv = 1.0f / sred[0];

    uint2 w;
    *(__half2*)&w.x = __floats2half2_rn(e0 * inv, e1 * inv);
    *(__half2*)&w.y = __floats2half2_rn(e2 * inv, e3 * inv);
    p[tid] = w;
}

// ---------------------------------------------------------------------------
extern "C" void kernel_launch(void* const* d_in, const int* in_sizes, int n_in,
                              void* d_out, int out_size) {
    (void)in_sizes; (void)n_in; (void)out_size;
    const float* inputs = (const float*)d_in[0];
    const float* gamma  = (const float*)d_in[1];
    const float* beta   = (const float*)d_in[2];
    const float* Wqkv   = (const float*)d_in[3];
    const float* bqkv   = (const float*)d_in[4];
    const float* Wout   = (const float*)d_in[5];
    const float* bout   = (const float*)d_in[6];
    float* out = (float*)d_out;

    const int smNT = 3 * (128 * 128 + 128 * 128);        // 98304
    const int smNN = 3 * (128 * 128 + 64 * 136 * 2);     // 101376
    cudaFuncSetAttribute(gemm_mma<0>, cudaFuncAttributeMaxDynamicSharedMemorySize, smNT);
    cudaFuncSetAttribute(gemm_mma<1>, cudaFuncAttributeMaxDynamicSharedMemorySize, smNT);
    cudaFuncSetAttribute(gemm_mma<2>, cudaFuncAttributeMaxDynamicSharedMemorySize, smNN);
    cudaFuncSetAttribute(gemm_mma<3>, cudaFuncAttributeMaxDynamicSharedMemorySize, smNN);

    conv_wqkv<<<(NQKV * C + 255) / 256, 256>>>(Wqkv, bqkv);
    f2h_wout<<<(C * C + 255) / 256, 256>>>(Wout);
    groupnorm_kernel<<<BNUM * G, 256>>>(inputs, gamma, beta);

    gemm_mma<0><<<dim3(NQKV / 128, MTOT / 128, 1), 128, smNT>>>(nullptr, nullptr, nullptr);
    gemm_mma<1><<<dim3(HW / 128, HW / 128, BNUM), 128, smNT>>>(nullptr, nullptr, nullptr);
    softmax_h<<<BNUM * HW, 256>>>();
    gemm_mma<2><<<dim3(C / 128, HW / 128, BNUM), 128, smNN>>>(nullptr, nullptr, nullptr);
    gemm_mma<3><<<dim3(C / 128, MTOT / 128, 1), 128, smNN>>>(bout, inputs, out);
}

// round 9
// speedup vs baseline: 7.4257x; 1.0396x over previous
#include <cuda_runtime.h>
#include <cuda_fp16.h>
#include <cstdint>
#include <cstddef>
#include <math.h>

#define BNUM 16
#define HW   1024
#define C    512
#define G    32
#define CG   16
#define NQKV 1536
#define MTOT (BNUM * HW)
#define SCALE 0.044194173824159216f   // 512^-0.5
#define NPERS 304                     // persistent CTAs (152 SMs x 2)

// fp16 scratch
__device__ __half g_xh[MTOT * C];
__device__ __half g_qh[MTOT * C];
__device__ __half g_kh[MTOT * C];
__device__ __half g_vh[MTOT * C];
__device__ __half g_sh[(size_t)BNUM * HW * HW];
__device__ __half g_oh[MTOT * C];
__device__ __half g_wqkvh[NQKV * C];   // permuted: [n'=e*512+ch][k], q-scale folded
__device__ __half g_wouth[C * C];
__device__ float  g_bqr[NQKV];         // permuted (scaled) qkv bias

// ---------------------------------------------------------------------------
// helpers
// ---------------------------------------------------------------------------
__device__ __forceinline__ uint32_t smaddr(const void* p) {
    return (uint32_t)__cvta_generic_to_shared(p);
}
__device__ __forceinline__ uint32_t swz(uint32_t off) {       // SW128 for 128B rows
    return off ^ ((off >> 3) & 0x70);
}
__device__ __forceinline__ void ldsm4(uint32_t a, uint32_t& r0, uint32_t& r1,
                                      uint32_t& r2, uint32_t& r3) {
    asm volatile("ldmatrix.sync.aligned.m8n8.x4.shared.b16 {%0,%1,%2,%3},[%4];"
                 : "=r"(r0), "=r"(r1), "=r"(r2), "=r"(r3) : "r"(a));
}
__device__ __forceinline__ void ldsm4t(uint32_t a, uint32_t& r0, uint32_t& r1,
                                       uint32_t& r2, uint32_t& r3) {
    asm volatile("ldmatrix.sync.aligned.m8n8.x4.trans.shared.b16 {%0,%1,%2,%3},[%4];"
                 : "=r"(r0), "=r"(r1), "=r"(r2), "=r"(r3) : "r"(a));
}
__device__ __forceinline__ void mma16816(float* d, const uint32_t* a, const uint32_t* b) {
    asm volatile(
        "mma.sync.aligned.m16n8k16.row.col.f32.f16.f16.f32 "
        "{%0,%1,%2,%3},{%4,%5,%6,%7},{%8,%9},{%0,%1,%2,%3};"
        : "+f"(d[0]), "+f"(d[1]), "+f"(d[2]), "+f"(d[3])
        : "r"(a[0]), "r"(a[1]), "r"(a[2]), "r"(a[3]), "r"(b[0]), "r"(b[1]));
}
#define CPA16(dst, src) \
    asm volatile("cp.async.cg.shared.global [%0],[%1],16;" ::"r"(dst), "l"(src))
#define CPCOMMIT() asm volatile("cp.async.commit_group;")
#define CPWAIT0()  asm volatile("cp.async.wait_group 0;")
#define CPWAIT1()  asm volatile("cp.async.wait_group 1;")

// ---------------------------------------------------------------------------
// weight converters (QKV permuted to [n'][k] + scale/bias folded)
// ---------------------------------------------------------------------------
__global__ void conv_wqkv(const float* __restrict__ W, const float* __restrict__ bq) {
    int idx = blockIdx.x * 256 + threadIdx.x;
    if (idx >= NQKV * C) return;
    int np = idx >> 9;          // n' = e*512 + ch
    int k  = idx & 511;
    int e  = np >> 9;
    int ch = np & 511;
    float s = (e == 0) ? SCALE : 1.0f;
    g_wqkvh[idx] = __float2half_rn(W[(size_t)k * NQKV + ch * 3 + e] * s);
    if (k == 0) g_bqr[np] = bq[ch * 3 + e] * s;
}
__global__ void f2h_wout(const float* __restrict__ s) {
    int i = blockIdx.x * 256 + threadIdx.x;
    if (i < C * C) g_wouth[i] = __float2half_rn(s[i]);
}

// ---------------------------------------------------------------------------
// GroupNorm -> fp16 g_xh (shuffle reduction, float2/half2)
// ---------------------------------------------------------------------------
__global__ void groupnorm_kernel(const float* __restrict__ in,
                                 const float* __restrict__ gamma,
                                 const float* __restrict__ beta) {
    int b = blockIdx.x >> 5;
    int g = blockIdx.x & 31;
    int tid = threadIdx.x, lane = tid & 31, warp = tid >> 5;
    const float* base = in + (size_t)b * HW * C + g * CG;
    float s = 0.f, ss = 0.f;
    for (int e = tid; e < HW * 8; e += 256) {       // float2 granules
        int pos = e >> 3, c2 = e & 7;
        float2 v = *(const float2*)(base + (size_t)pos * C + c2 * 2);
        s += v.x + v.y; ss += v.x * v.x + v.y * v.y;
    }
#pragma unroll
    for (int o = 16; o; o >>= 1) {
        s  += __shfl_xor_sync(0xffffffffu, s, o);
        ss += __shfl_xor_sync(0xffffffffu, ss, o);
    }
    __shared__ float sm_s[8], sm_ss[8];
    if (lane == 0) { sm_s[warp] = s; sm_ss[warp] = ss; }
    __syncthreads();
    float ts = 0.f, tss = 0.f;
#pragma unroll
    for (int i = 0; i < 8; i++) { ts += sm_s[i]; tss += sm_ss[i]; }
    const float invN = 1.0f / (HW * CG);
    float mean = ts * invN;
    float var  = tss * invN - mean * mean;
    float rstd = rsqrtf(var + 1e-3f);
    __half* outb = g_xh + (size_t)b * HW * C + g * CG;
    for (int e = tid; e < HW * 8; e += 256) {
        int pos = e >> 3, c2 = e & 7;
        float2 v = *(const float2*)(base + (size_t)pos * C + c2 * 2);
        float g0 = gamma[g * CG + c2 * 2], g1 = gamma[g * CG + c2 * 2 + 1];
        float b0 = beta[g * CG + c2 * 2],  b1 = beta[g * CG + c2 * 2 + 1];
        *(__half2*)(outb + (size_t)pos * C + c2 * 2) =
            __floats2half2_rn((v.x - mean) * rstd * g0 + b0,
                              (v.y - mean) * rstd * g1 + b1);
    }
}

// ---------------------------------------------------------------------------
// Persistent fp16 mma.sync GEMM: 128 thr (2x2 warps, 64x64 warp tile),
// block tile 128x128, BK=64, 3-stage cp.async (distance 2), 1 barrier/step,
// frag ping-pong, SW128 swizzle, 2 CTAs/SM, NPERS persistent CTAs.
// Pipeline flows across tile boundaries; epilogue overlaps next tile's loads.
// EPI 0: X @ Wqkv' (NT) -> q/k/v (bias folded)      tiles 12x128
// EPI 1: Q @ K^T  (NT, per batch) -> fp16 scores     tiles 8x8x16
// EPI 2: P @ V    (NN, per batch) -> fp16 O          tiles 4x8x16
// EPI 3: O @ W_out + bias + residual -> fp32 out     tiles 4x128
// ---------------------------------------------------------------------------
template <int EPI>
__global__ void __launch_bounds__(128, 2)
gemm_mma(const float* __restrict__ bias,
         const float* __restrict__ resid,
         float* __restrict__ outF) {
    constexpr bool NT  = (EPI <= 1);
    constexpr int  K   = (EPI == 2) ? 1024 : 512;
    constexpr int  KT  = K / 64;
    constexpr int  LDA = (EPI == 2) ? 1024 : 512;
    constexpr int  LDB = 512;
    constexpr int  TX  = (EPI == 0) ? 12 : ((EPI == 1) ? 8 : 4);
    constexpr int  TY  = (EPI == 1 || EPI == 2) ? 8 : 128;
    constexpr int  TZ  = (EPI == 1 || EPI == 2) ? 16 : 1;
    constexpr int  T   = TX * TY * TZ;

    constexpr int ASTG_B = 128 * 128;
    constexpr int BSTG_B = NT ? (128 * 128) : (64 * 136 * 2);
    extern __shared__ char smc[];
    char* Abuf = smc;
    char* Bbuf = smc + 3 * ASTG_B;

    int tid = threadIdx.x, lane = tid & 31, warp = tid >> 5;
    int wm = warp & 1, wn = warp >> 1;
    int bid = blockIdx.x;
    int GP = gridDim.x;
    int myN = (bid < T) ? ((T - 1 - bid) / GP + 1) : 0;
    int S = myN * KT;

    float acc[4][8][4] = {};

    // resolve tile i (my i-th tile) -> m0, n0, z
    auto tileinfo = [&](int i, int& m0, int& n0, int& z) {
        int t = bid + i * GP;
        int x = t % TX;
        int y = (t / TX) % TY;
        z = t / (TX * TY);
        m0 = y * 128; n0 = x * 128;
    };

    auto load = [&](int s) {
        int i = s / KT;
        if (i < myN) {
            int m0, n0, z;
            tileinfo(i, m0, n0, z);
            int k0 = (s % KT) * 64;
            const __half* A;
            const __half* B;
            if constexpr (EPI == 0)      { A = g_xh;                        B = g_wqkvh; }
            else if constexpr (EPI == 1) { A = g_qh + (size_t)z * HW * C;   B = g_kh + (size_t)z * HW * C; }
            else if constexpr (EPI == 2) { A = g_sh + (size_t)z * HW * HW;  B = g_vh + (size_t)z * HW * C; }
            else                         { A = g_oh;                        B = g_wouth; }
            int st = s % 3;
            uint32_t Asm = smaddr(Abuf + st * ASTG_B);
            uint32_t Bsm = smaddr(Bbuf + st * BSTG_B);
#pragma unroll
            for (int q = 0; q < 8; q++) {
                int c = tid + q * 128;
                int r = c >> 3, ch = c & 7;
                CPA16(Asm + swz((uint32_t)(r * 128 + ch * 16)),
                      A + (size_t)(m0 + r) * LDA + k0 + ch * 8);
            }
            if constexpr (NT) {
#pragma unroll
                for (int q = 0; q < 8; q++) {
                    int c = tid + q * 128;
                    int r = c >> 3, ch = c & 7;
                    CPA16(Bsm + swz((uint32_t)(r * 128 + ch * 16)),
                          B + (size_t)(n0 + r) * LDB + k0 + ch * 8);
                }
            } else {
#pragma unroll
                for (int q = 0; q < 8; q++) {
                    int c = tid + q * 128;
                    int r = c >> 4, ch = c & 15;
                    CPA16(Bsm + (uint32_t)(r * 272 + ch * 16),
                          B + (size_t)(k0 + r) * LDB + n0 + ch * 8);
                }
            }
        }
        CPCOMMIT();
    };

    auto ldfrag = [&](int st, int ks, uint32_t a[4][4], uint32_t b[8][2]) {
        uint32_t Asm = smaddr(Abuf + st * ASTG_B);
        uint32_t Bsm = smaddr(Bbuf + st * BSTG_B);
        int colh = ks + ((lane >> 4) << 3);
#pragma unroll
        for (int mt = 0; mt < 4; mt++) {
            int r = wm * 64 + mt * 16 + (lane & 15);
            ldsm4(Asm + swz((uint32_t)(r * 128 + colh * 2)),
                  a[mt][0], a[mt][1], a[mt][2], a[mt][3]);
        }
        if constexpr (NT) {
#pragma unroll
            for (int ng = 0; ng < 4; ng++) {
                int r = wn * 64 + ng * 16 + (lane & 15);
                uint32_t r0, r1, r2, r3;
                ldsm4(Bsm + swz((uint32_t)(r * 128 + colh * 2)), r0, r1, r2, r3);
                b[2 * ng][0] = r0; b[2 * ng][1] = r2;
                b[2 * ng + 1][0] = r1; b[2 * ng + 1][1] = r3;
            }
        } else {
#pragma unroll
            for (int ng = 0; ng < 4; ng++) {
                int r = ks + (lane & 15);
                int col = wn * 64 + ng * 16 + ((lane >> 4) << 3);
                uint32_t r0, r1, r2, r3;
                ldsm4t(Bsm + (uint32_t)(r * 272 + col * 2), r0, r1, r2, r3);
                b[2 * ng][0] = r0; b[2 * ng][1] = r1;
                b[2 * ng + 1][0] = r2; b[2 * ng + 1][1] = r3;
            }
        }
    };

    auto mma_all = [&](uint32_t a[4][4], uint32_t b[8][2]) {
#pragma unroll
        for (int mt = 0; mt < 4; mt++)
#pragma unroll
            for (int nt = 0; nt < 8; nt++) mma16816(acc[mt][nt], a[mt], b[nt]);
    };

    load(0);
    load(1);

    for (int s = 0; s < S; s++) {
        if (s + 1 < S) { CPWAIT1(); } else { CPWAIT0(); }
        __syncthreads();
        load(s + 2);
        int st = s % 3;
        uint32_t a0[4][4], b0[8][2], a1[4][4], b1[8][2];
        ldfrag(st, 0,  a0, b0);
        ldfrag(st, 16, a1, b1);
        mma_all(a0, b0);
        ldfrag(st, 32, a0, b0);
        mma_all(a1, b1);
        ldfrag(st, 48, a1, b1);
        mma_all(a0, b0);
        mma_all(a1, b1);

        if ((s + 1) % KT == 0) {
            // ---- epilogue for tile s/KT (overlaps already-in-flight loads) ----
            int m0, n0, z;
            tileinfo(s / KT, m0, n0, z);
#pragma unroll
            for (int mt = 0; mt < 4; mt++) {
#pragma unroll
                for (int nt = 0; nt < 8; nt++) {
                    int r  = m0 + wm * 64 + mt * 16 + (lane >> 2);
                    int nl = wn * 64 + nt * 8 + (lane & 3) * 2;
                    float* v = acc[mt][nt];
                    if constexpr (EPI == 0) {
                        int e = n0 >> 9;
                        __half* dst = (e == 0) ? g_qh : ((e == 1) ? g_kh : g_vh);
                        int ch = (n0 & 511) + nl;
                        float b0f = g_bqr[n0 + nl], b1f = g_bqr[n0 + nl + 1];
                        *(__half2*)&dst[(size_t)r * C + ch] =
                            __floats2half2_rn(v[0] + b0f, v[1] + b1f);
                        *(__half2*)&dst[(size_t)(r + 8) * C + ch] =
                            __floats2half2_rn(v[2] + b0f, v[3] + b1f);
                    } else if constexpr (EPI == 1) {
                        size_t base = (size_t)z * HW * HW;
                        int cc = n0 + nl;
                        *(__half2*)&g_sh[base + (size_t)r * HW + cc] =
                            __floats2half2_rn(v[0], v[1]);
                        *(__half2*)&g_sh[base + (size_t)(r + 8) * HW + cc] =
                            __floats2half2_rn(v[2], v[3]);
                    } else if constexpr (EPI == 2) {
                        size_t base = (size_t)z * HW * C;
                        int cc = n0 + nl;
                        *(__half2*)&g_oh[base + (size_t)r * C + cc] =
                            __floats2half2_rn(v[0], v[1]);
                        *(__half2*)&g_oh[base + (size_t)(r + 8) * C + cc] =
                            __floats2half2_rn(v[2], v[3]);
                    } else {
                        int cc = n0 + nl;
                        outF[(size_t)r * C + cc]     = v[0] + bias[cc]     + resid[(size_t)r * C + cc];
                        outF[(size_t)r * C + cc + 1] = v[1] + bias[cc + 1] + resid[(size_t)r * C + cc + 1];
                        outF[(size_t)(r + 8) * C + cc]     = v[2] + bias[cc]     + resid[(size_t)(r + 8) * C + cc];
                        outF[(size_t)(r + 8) * C + cc + 1] = v[3] + bias[cc + 1] + resid[(size_t)(r + 8) * C + cc + 1];
                    }
                }
            }
            // zero accumulators for next tile
#pragma unroll
            for (int mt = 0; mt < 4; mt++)
#pragma unroll
                for (int nt = 0; nt < 8; nt++)
#pragma unroll
                    for (int j = 0; j < 4; j++) acc[mt][nt][j] = 0.f;
        }
    }
}

// ---------------------------------------------------------------------------
// fp16 in-place row softmax over 1024 cols: 128 thr, uint4/thread, 2 barriers
// ---------------------------------------------------------------------------
__global__ void softmax_h() {
    size_t row = blockIdx.x;
    uint4* p = (uint4*)(g_sh + row * HW);
    int tid = threadIdx.x, lane = tid & 31, warp = tid >> 5;
    uint4 raw = p[tid];
    __half2 h[4] = {*(__half2*)&raw.x, *(__half2*)&raw.y,
                    *(__half2*)&raw.z, *(__half2*)&raw.w};
    float2 f[4];
#pragma unroll
    for (int i = 0; i < 4; i++) f[i] = __half22float2(h[i]);

    float m = -1e30f;
#pragma unroll
    for (int i = 0; i < 4; i++) m = fmaxf(m, fmaxf(f[i].x, f[i].y));
#pragma unroll
    for (int o = 16; o; o >>= 1) m = fmaxf(m, __shfl_xor_sync(0xffffffffu, m, o));
    __shared__ float smax[4], ssum[4];
    if (lane == 0) smax[warp] = m;
    __syncthreads();
    m = fmaxf(fmaxf(smax[0], smax[1]), fmaxf(smax[2], smax[3]));

    float e[8];
    float s = 0.f;
#pragma unroll
    for (int i = 0; i < 4; i++) {
        e[2 * i]     = __expf(f[i].x - m);
        e[2 * i + 1] = __expf(f[i].y - m);
        s += e[2 * i] + e[2 * i + 1];
    }
#pragma unroll
    for (int o = 16; o; o >>= 1) s += __shfl_xor_sync(0xffffffffu, s, o);
    if (lane == 0) ssum[warp] = s;
    __syncthreads();
    float inv = 1.0f / (ssum[0] + ssum[1] + ssum[2] + ssum[3]);

    uint4 w;
    *(__half2*)&w.x = __floats2half2_rn(e[0] * inv, e[1] * inv);
    *(__half2*)&w.y = __floats2half2_rn(e[2] * inv, e[3] * inv);
    *(__half2*)&w.z = __floats2half2_rn(e[4] * inv, e[5] * inv);
    *(__half2*)&w.w = __floats2half2_rn(e[6] * inv, e[7] * inv);
    p[tid] = w;
}

// ---------------------------------------------------------------------------
extern "C" void kernel_launch(void* const* d_in, const int* in_sizes, int n_in,
                              void* d_out, int out_size) {
    (void)in_sizes; (void)n_in; (void)out_size;
    const float* inputs = (const float*)d_in[0];
    const float* gamma  = (const float*)d_in[1];
    const float* beta   = (const float*)d_in[2];
    const float* Wqkv   = (const float*)d_in[3];
    const float* bqkv   = (const float*)d_in[4];
    const float* Wout   = (const float*)d_in[5];
    const float* bout   = (const float*)d_in[6];
    float* out = (float*)d_out;

    const int smNT = 3 * (128 * 128 + 128 * 128);        // 98304
    const int smNN = 3 * (128 * 128 + 64 * 136 * 2);     // 101376
    cudaFuncSetAttribute(gemm_mma<0>, cudaFuncAttributeMaxDynamicSharedMemorySize, smNT);
    cudaFuncSetAttribute(gemm_mma<1>, cudaFuncAttributeMaxDynamicSharedMemorySize, smNT);
    cudaFuncSetAttribute(gemm_mma<2>, cudaFuncAttributeMaxDynamicSharedMemorySize, smNN);
    cudaFuncSetAttribute(gemm_mma<3>, cudaFuncAttributeMaxDynamicSharedMemorySize, smNN);

    conv_wqkv<<<(NQKV * C + 255) / 256, 256>>>(Wqkv, bqkv);
    f2h_wout<<<(C * C + 255) / 256, 256>>>(Wout);
    groupnorm_kernel<<<BNUM * G, 256>>>(inputs, gamma, beta);

    gemm_mma<0><<<NPERS, 128, smNT>>>(nullptr, nullptr, nullptr);
    gemm_mma<1><<<NPERS, 128, smNT>>>(nullptr, nullptr, nullptr);
    softmax_h<<<BNUM * HW, 128>>>();
    gemm_mma<2><<<NPERS, 128, smNN>>>(nullptr, nullptr, nullptr);
    gemm_mma<3><<<NPERS, 128, smNN>>>(bout, inputs, out);
}